// round 1
// baseline (speedup 1.0000x reference)
#include <cuda_runtime.h>
#include <math.h>

#define NN 50000
#define EE 400000
#define DD 128
#define CC 8

#define TILE_E 64
#define XS 268   // xs row stride (264 used)
#define MS 132   // intermediate row stride (128 used)

// ---------------- device scratch (no allocations allowed) ----------------
__device__ float g_node_agg[NN * DD];        // 25.6 MB
__device__ float g_coord_sum[NN * CC * 3];   // 4.8 MB
__device__ float g_cnt[NN];
__device__ float g_pcol[NN * 3];
__device__ int   g_csum[NN];
__device__ unsigned int g_maxbits;

__device__ __forceinline__ float silu_f(float x) {
    return x * (1.0f / (1.0f + __expf(-x)));
}

// ---------------- zero scratch ----------------
__global__ void zero_kernel() {
    long t0 = (long)blockIdx.x * blockDim.x + threadIdx.x;
    long stride = (long)gridDim.x * blockDim.x;
    for (long i = t0; i < (long)NN * DD; i += stride) g_node_agg[i] = 0.f;
    for (long i = t0; i < (long)NN * 24; i += stride) g_coord_sum[i] = 0.f;
    for (long i = t0; i < NN; i += stride) g_cnt[i] = 0.f;
    if (t0 == 0) g_maxbits = 0u;
}

// ---------------- per-node precompute: csum, pooled_col ----------------
__global__ void node_pre_kernel(const float* __restrict__ coords,
                                const float* __restrict__ cw) {
    int n = blockIdx.x * blockDim.x + threadIdx.x;
    if (n >= NN) return;
    float px = 0.f, py = 0.f, pz = 0.f;
    int cs = 0;
#pragma unroll
    for (int c = 0; c < 8; c++) {
        float w = cw[n * 8 + c];
        if (w != 0.f) {
            cs++;
            px += coords[n * 24 + c * 3 + 0];
            py += coords[n * 24 + c * 3 + 1];
            pz += coords[n * 24 + c * 3 + 2];
        }
    }
    float inv = 1.f / ((float)cs + 0.001f);
    g_pcol[n * 3 + 0] = px * inv;
    g_pcol[n * 3 + 1] = py * inv;
    g_pcol[n * 3 + 2] = pz * inv;
    g_csum[n] = cs;
}

// ---------------- global max of squared channel distances ----------------
__global__ void max_kernel(const float* __restrict__ coords,
                           const int* __restrict__ el) {
    int e = blockIdx.x * blockDim.x + threadIdx.x;
    float m = 0.f;
    if (e < EE) {
        int src = el[e * 3 + 0];
        int tgt = el[e * 3 + 1];
        float ct[24], cs[24];
#pragma unroll
        for (int i = 0; i < 24; i++) {
            ct[i] = coords[(long)tgt * 24 + i];
            cs[i] = coords[(long)src * 24 + i];
        }
#pragma unroll
        for (int c = 0; c < 8; c++) {
#pragma unroll
            for (int d = 0; d < 8; d++) {
                float dx = ct[c * 3 + 0] - cs[d * 3 + 0];
                float dy = ct[c * 3 + 1] - cs[d * 3 + 1];
                float dz = ct[c * 3 + 2] - cs[d * 3 + 2];
                float ns = dx * dx + dy * dy + dz * dz;
                m = fmaxf(m, ns);
            }
        }
    }
#pragma unroll
    for (int o = 16; o > 0; o >>= 1)
        m = fmaxf(m, __shfl_xor_sync(0xffffffffu, m, o));
    if ((threadIdx.x & 31) == 0)
        atomicMax(&g_maxbits, __float_as_uint(m));  // valid for non-negative floats
}

// ---------------- fused edge kernel ----------------
struct EdgeSmem {
    float xs[TILE_E * XS];     // x = [h_tgt | h_src | radial] tiles
    float ms1[TILE_E * MS];    // m1 / cf reuse
    float ms2[TILE_E * MS];    // m (post-GEMM2)
    float wscr[8][320];        // per-warp: At(0) Bs(64) M(128) T(192) cwt(256) cws(264) ct(272) cs(296)
    float cw2s[DD * 8];        // staged c_w2
    float cdiff[TILE_E * 24];
    float ef[TILE_E * 8];
    int   s_tgt[TILE_E];
    float s_ew[TILE_E];
    float s_wr[TILE_E];
    int   s_ts[TILE_E];
};

template <int KQ>
__device__ __forceinline__ void tile_gemm(const float* __restrict__ src, int sstride,
                                          const float* __restrict__ W,
                                          const float* __restrict__ bias,
                                          float* __restrict__ dst, int tid) {
    const int cg = tid & 31;   // 32 column groups of 4
    const int eg = tid >> 5;   // 8 edge groups of 8
    float acc[8][4];
#pragma unroll
    for (int r = 0; r < 8; r++) {
        acc[r][0] = 0.f; acc[r][1] = 0.f; acc[r][2] = 0.f; acc[r][3] = 0.f;
    }
    const float4* Wv = (const float4*)W;   // [K][32] of float4
#pragma unroll 2
    for (int kq = 0; kq < KQ; kq++) {
        float4 w0 = Wv[(kq * 4 + 0) * 32 + cg];
        float4 w1 = Wv[(kq * 4 + 1) * 32 + cg];
        float4 w2 = Wv[(kq * 4 + 2) * 32 + cg];
        float4 w3 = Wv[(kq * 4 + 3) * 32 + cg];
#pragma unroll
        for (int r = 0; r < 8; r++) {
            float4 xv = *(const float4*)&src[(eg * 8 + r) * sstride + kq * 4];
            acc[r][0] = fmaf(xv.x, w0.x, fmaf(xv.y, w1.x, fmaf(xv.z, w2.x, fmaf(xv.w, w3.x, acc[r][0]))));
            acc[r][1] = fmaf(xv.x, w0.y, fmaf(xv.y, w1.y, fmaf(xv.z, w2.y, fmaf(xv.w, w3.y, acc[r][1]))));
            acc[r][2] = fmaf(xv.x, w0.z, fmaf(xv.y, w1.z, fmaf(xv.z, w2.z, fmaf(xv.w, w3.z, acc[r][2]))));
            acc[r][3] = fmaf(xv.x, w0.w, fmaf(xv.y, w1.w, fmaf(xv.z, w2.w, fmaf(xv.w, w3.w, acc[r][3]))));
        }
    }
    float4 bb = *(const float4*)&bias[cg * 4];
#pragma unroll
    for (int r = 0; r < 8; r++) {
        float4 o;
        o.x = silu_f(acc[r][0] + bb.x);
        o.y = silu_f(acc[r][1] + bb.y);
        o.z = silu_f(acc[r][2] + bb.z);
        o.w = silu_f(acc[r][3] + bb.w);
        *(float4*)&dst[(eg * 8 + r) * MS + cg * 4] = o;
    }
}

__global__ void edge_kernel(const float* __restrict__ h,
                            const float* __restrict__ coords,
                            const float* __restrict__ ca,
                            const float* __restrict__ cw,
                            const float* __restrict__ edge_weights,
                            const int* __restrict__ el,
                            const float* __restrict__ rl_w,
                            const float* __restrict__ rl_b,
                            const float* __restrict__ m_w1,
                            const float* __restrict__ m_b1,
                            const float* __restrict__ m_w2,
                            const float* __restrict__ m_b2,
                            const float* __restrict__ c_w1,
                            const float* __restrict__ c_b1,
                            const float* __restrict__ c_w2,
                            const float* __restrict__ w_r) {
    extern __shared__ char smem_raw[];
    EdgeSmem& sm = *reinterpret_cast<EdgeSmem*>(smem_raw);

    const int tid = threadIdx.x;
    const int wid = tid >> 5;
    const int lane = tid & 31;
    const long tileBase = (long)blockIdx.x * TILE_E;

    float gmax = sqrtf(__uint_as_float(g_maxbits));
    float inv_g = 1.f / (gmax + 0.001f);

    // stage c_w2 (128x8)
    for (int i = tid; i < DD * 8; i += blockDim.x) sm.cw2s[i] = c_w2[i];

    float* WS  = &sm.wscr[wid][0];
    float* At  = WS;
    float* Bs  = WS + 64;
    float* Mm  = WS + 128;
    float* Tt  = WS + 192;
    float* cwt = WS + 256;
    float* cws = WS + 264;
    float* ctb = WS + 272;
    float* csb = WS + 296;

    // ---- Phase A: per-edge preprocessing (each warp handles 8 edges) ----
    for (int i = 0; i < 8; i++) {
        int e = wid * 8 + i;
        long ge = tileBase + e;
        bool valid = (ge < (long)EE);
        int src = 0, tgt = 0, rel = 0;
        if (valid) {
            src = el[ge * 3 + 0];
            tgt = el[ge * 3 + 1];
            rel = el[ge * 3 + 2];
        }
        if (lane == 0) {
            sm.s_tgt[e] = valid ? tgt : -1;
            sm.s_ew[e]  = valid ? edge_weights[ge] : 0.f;
            sm.s_wr[e]  = valid ? w_r[rel] : 0.f;
            int cs = valid ? g_csum[tgt] : 1;
            int ts = cs - 1;
            ts = ts < 0 ? 0 : (ts > 7 ? 7 : ts);
            sm.s_ts[e] = ts;
        }
        if (!valid) {
            for (int k = lane; k < 264; k += 32) sm.xs[e * XS + k] = 0.f;
            for (int k = lane; k < 24;  k += 32) sm.cdiff[e * 24 + k] = 0.f;
            __syncwarp();
            continue;
        }
        // stage per-edge operands
        At[lane]      = ca[(long)tgt * 64 + lane];
        At[lane + 32] = ca[(long)tgt * 64 + lane + 32];
        Bs[lane]      = ca[(long)src * 64 + lane];
        Bs[lane + 32] = ca[(long)src * 64 + lane + 32];
        if (lane < 8) { cwt[lane] = cw[(long)tgt * 8 + lane]; cws[lane] = cw[(long)src * 8 + lane]; }
        if (lane < 24) { ctb[lane] = coords[(long)tgt * 24 + lane]; csb[lane] = coords[(long)src * 24 + lane]; }
        __syncwarp();

        // M[c][d] = (||ct_c - cs_d|| / (gmax+eps)) * cwt[c]*cws[d]
#pragma unroll
        for (int half = 0; half < 2; half++) {
            int idx = lane + half * 32;
            int c = idx >> 3, d = idx & 7;
            float dx = ctb[c * 3 + 0] - csb[d * 3 + 0];
            float dy = ctb[c * 3 + 1] - csb[d * 3 + 1];
            float dz = ctb[c * 3 + 2] - csb[d * 3 + 2];
            float ns = dx * dx + dy * dy + dz * dz;
            float nrm = (ns > 0.f) ? ns * rsqrtf(ns) : 0.f;
            Mm[idx] = nrm * inv_g * cwt[c] * cws[d];
        }
        __syncwarp();

        // T[a][d] = sum_c At[c][a] * M[c][d]
#pragma unroll
        for (int half = 0; half < 2; half++) {
            int idx = lane + half * 32;
            int a = idx >> 3, d = idx & 7;
            float t = 0.f;
#pragma unroll
            for (int c = 0; c < 8; c++) t = fmaf(At[c * 8 + a], Mm[c * 8 + d], t);
            Tt[idx] = t;
        }
        __syncwarp();

        // R[a][b] = sum_d T[a][d] * Bs[d][b]
        float r0 = 0.f, r1 = 0.f;
        {
            int a = lane >> 3, b = lane & 7;
#pragma unroll
            for (int d = 0; d < 8; d++) r0 = fmaf(Tt[a * 8 + d], Bs[d * 8 + b], r0);
            int idx = lane + 32;
            a = idx >> 3; b = idx & 7;
#pragma unroll
            for (int d = 0; d < 8; d++) r1 = fmaf(Tt[a * 8 + d], Bs[d * 8 + b], r1);
        }
        float ss = r0 * r0 + r1 * r1;
#pragma unroll
        for (int o = 16; o > 0; o >>= 1) ss += __shfl_xor_sync(0xffffffffu, ss, o);
        float invn = 1.f / (sqrtf(ss) + 0.001f);
        Mm[lane] = r0;           // reuse M as flattened R
        Mm[lane + 32] = r1;
        __syncwarp();

        // radial_out[j] = (R . rl_w[:,j]) * invn + rl_b[j]  -> xs[e][256+j]
        if (lane < 8) {
            float acc = 0.f;
#pragma unroll
            for (int k = 0; k < 64; k++) acc = fmaf(Mm[k], rl_w[k * 8 + lane], acc);
            sm.xs[e * XS + 256 + lane] = acc * invn + rl_b[lane];
        }
        // gather h[tgt], h[src] -> xs[e][0..255]
        ((float4*)&sm.xs[e * XS])[lane]      = ((const float4*)(h + (long)tgt * 128))[lane];
        ((float4*)&sm.xs[e * XS])[lane + 32] = ((const float4*)(h + (long)src * 128))[lane];
        // coord_diff = coords[tgt] - pooled_col[src]
        if (lane < 24) {
            int k = lane % 3;
            sm.cdiff[e * 24 + lane] = ctb[lane] - g_pcol[(long)src * 3 + k];
        }
        __syncwarp();
    }
    __syncthreads();

    // ---- GEMM chain ----
    tile_gemm<66>(sm.xs,  XS, m_w1, m_b1, sm.ms1, tid);  // m1 = silu(x@W1+b1)
    __syncthreads();
    tile_gemm<32>(sm.ms1, MS, m_w2, m_b2, sm.ms2, tid);  // m  = silu(m1@W2+b2)
    __syncthreads();
    tile_gemm<32>(sm.ms2, MS, c_w1, c_b1, sm.ms1, tid);  // cf = silu(m@Cw1+Cb1)
    __syncthreads();

    // edge_feat = cf @ c_w2  (64 edges x 8)
    {
        int e = tid >> 2;
        int jj = tid & 3;
        float a0 = 0.f, a1 = 0.f;
#pragma unroll 8
        for (int k = 0; k < 128; k++) {
            float cf = sm.ms1[e * MS + k];
            a0 = fmaf(cf, sm.cw2s[k * 8 + jj * 2 + 0], a0);
            a1 = fmaf(cf, sm.cw2s[k * 8 + jj * 2 + 1], a1);
        }
        sm.ef[e * 8 + jj * 2 + 0] = a0;
        sm.ef[e * 8 + jj * 2 + 1] = a1;
    }
    __syncthreads();

    // ---- aggregation atomics ----
    // node_agg[tgt] += m * ew
    for (int idx = tid; idx < TILE_E * 128; idx += 256) {
        int e = idx >> 7, j = idx & 127;
        int t = sm.s_tgt[e];
        if (t >= 0)
            atomicAdd(&g_node_agg[(long)t * 128 + j], sm.ms2[e * MS + j] * sm.s_ew[e]);
    }
    // coord_sum[tgt] += w_r * coord_diff * pooled_edge
    for (int idx = tid; idx < TILE_E * 8; idx += 256) {
        int e = idx >> 3, a = idx & 7;
        int t = sm.s_tgt[e];
        if (t < 0) continue;
        int ts = sm.s_ts[e];
        int w = 8 - ts;
        int hi = a + w; if (hi > 8) hi = 8;
        float s = 0.f;
        for (int b = a; b < hi; b++) s += sm.ef[e * 8 + b];
        float pe = (s / (float)w) * sm.s_wr[e];
#pragma unroll
        for (int k = 0; k < 3; k++)
            atomicAdd(&g_coord_sum[(long)t * 24 + a * 3 + k], sm.cdiff[e * 24 + a * 3 + k] * pe);
    }
    // cnt[tgt] += 1
    if (tid < TILE_E) {
        int t = sm.s_tgt[tid];
        if (t >= 0) atomicAdd(&g_cnt[t], 1.f);
    }
}

// ---------------- node epilogue: out GEMM + BN + silu + residuals ----------------
__global__ void node_out_kernel(const float* __restrict__ h,
                                const float* __restrict__ coords,
                                const float* __restrict__ het_w,
                                const float* __restrict__ het_b,
                                const float* __restrict__ gamma,
                                const float* __restrict__ beta,
                                float* __restrict__ out) {
    __shared__ float ag[64 * MS];
    const int tid = threadIdx.x;
    const int base = blockIdx.x * 64;
    const float INVS = 0.9999950000374996f;  // 1/sqrt(1+1e-5)

    for (int idx = tid; idx < 64 * 128; idx += 256) {
        int n = idx >> 7, k = idx & 127;
        int gn = base + n;
        ag[n * MS + k] = (gn < NN) ? g_node_agg[(long)gn * 128 + k] : 0.f;
    }
    __syncthreads();

    const int cg = tid & 31;
    const int ng = tid >> 5;
    float acc[8][4];
#pragma unroll
    for (int r = 0; r < 8; r++) { acc[r][0] = acc[r][1] = acc[r][2] = acc[r][3] = 0.f; }
    const float4* Wv = (const float4*)het_w;
#pragma unroll 2
    for (int kq = 0; kq < 32; kq++) {
        float4 w0 = Wv[(kq * 4 + 0) * 32 + cg];
        float4 w1 = Wv[(kq * 4 + 1) * 32 + cg];
        float4 w2 = Wv[(kq * 4 + 2) * 32 + cg];
        float4 w3 = Wv[(kq * 4 + 3) * 32 + cg];
#pragma unroll
        for (int r = 0; r < 8; r++) {
            float4 xv = *(const float4*)&ag[(ng * 8 + r) * MS + kq * 4];
            acc[r][0] = fmaf(xv.x, w0.x, fmaf(xv.y, w1.x, fmaf(xv.z, w2.x, fmaf(xv.w, w3.x, acc[r][0]))));
            acc[r][1] = fmaf(xv.x, w0.y, fmaf(xv.y, w1.y, fmaf(xv.z, w2.y, fmaf(xv.w, w3.y, acc[r][1]))));
            acc[r][2] = fmaf(xv.x, w0.z, fmaf(xv.y, w1.z, fmaf(xv.z, w2.z, fmaf(xv.w, w3.z, acc[r][2]))));
            acc[r][3] = fmaf(xv.x, w0.w, fmaf(xv.y, w1.w, fmaf(xv.z, w2.w, fmaf(xv.w, w3.w, acc[r][3]))));
        }
    }
    int j0 = cg * 4;
    float4 hb = *(const float4*)&het_b[j0];
    float4 gm = *(const float4*)&gamma[j0];
    float4 bt = *(const float4*)&beta[j0];
#pragma unroll
    for (int r = 0; r < 8; r++) {
        int gn = base + ng * 8 + r;
        if (gn < NN) {
            float4 o;
            o.x = silu_f((acc[r][0] + hb.x) * INVS * gm.x + bt.x);
            o.y = silu_f((acc[r][1] + hb.y) * INVS * gm.y + bt.y);
            o.z = silu_f((acc[r][2] + hb.z) * INVS * gm.z + bt.z);
            o.w = silu_f((acc[r][3] + hb.w) * INVS * gm.w + bt.w);
            float4 hv = *(const float4*)&h[(long)gn * 128 + j0];
            o.x += hv.x; o.y += hv.y; o.z += hv.z; o.w += hv.w;
            *(float4*)&out[(long)gn * 128 + j0] = o;
        }
    }

    // coord_output = coords + coord_sum / max(cnt,1)
    for (int idx = tid; idx < 64 * 24; idx += 256) {
        int n = idx / 24, k = idx % 24;
        int gn = base + n;
        if (gn < NN) {
            float c = fmaxf(g_cnt[gn], 1.f);
            out[(long)NN * 128 + (long)gn * 24 + k] =
                coords[(long)gn * 24 + k] + g_coord_sum[(long)gn * 24 + k] / c;
        }
    }
}

// ---------------- launch ----------------
extern "C" void kernel_launch(void* const* d_in, const int* in_sizes, int n_in,
                              void* d_out, int out_size) {
    (void)in_sizes; (void)n_in; (void)out_size;
    const float* h      = (const float*)d_in[0];
    const float* coords = (const float*)d_in[1];
    const float* ca     = (const float*)d_in[2];
    const float* cw     = (const float*)d_in[3];
    const float* ew     = (const float*)d_in[4];
    const int*   el     = (const int*)d_in[5];
    const float* rl_w   = (const float*)d_in[6];
    const float* rl_b   = (const float*)d_in[7];
    const float* m_w1   = (const float*)d_in[8];
    const float* m_b1   = (const float*)d_in[9];
    const float* m_w2   = (const float*)d_in[10];
    const float* m_b2   = (const float*)d_in[11];
    const float* c_w1   = (const float*)d_in[12];
    const float* c_b1   = (const float*)d_in[13];
    const float* c_w2   = (const float*)d_in[14];
    const float* het_w  = (const float*)d_in[15];
    const float* het_b  = (const float*)d_in[16];
    const float* gamma  = (const float*)d_in[17];
    const float* beta   = (const float*)d_in[18];
    const float* w_r    = (const float*)d_in[19];
    float* out = (float*)d_out;

    cudaFuncSetAttribute(edge_kernel, cudaFuncAttributeMaxDynamicSharedMemorySize,
                         (int)sizeof(EdgeSmem));

    zero_kernel<<<2048, 256>>>();
    node_pre_kernel<<<(NN + 255) / 256, 256>>>(coords, cw);
    max_kernel<<<(EE + 255) / 256, 256>>>(coords, el);
    edge_kernel<<<(EE + TILE_E - 1) / TILE_E, 256, sizeof(EdgeSmem)>>>(
        h, coords, ca, cw, ew, el, rl_w, rl_b,
        m_w1, m_b1, m_w2, m_b2, c_w1, c_b1, c_w2, w_r);
    node_out_kernel<<<(NN + 63) / 64, 256>>>(h, coords, het_w, het_b, gamma, beta, out);
}

// round 2
// speedup vs baseline: 1.1067x; 1.1067x over previous
#include <cuda_runtime.h>
#include <math.h>

#define NN 50000
#define EE 400000
#define DD 128
#define CC 8

#define TILE_E 64
#define XS 268   // xs row stride in floats (264 used, 8B-aligned rows)
#define MS 132   // intermediate row stride (128 used, 8B-aligned rows)

// ---------------- device scratch (no allocations allowed) ----------------
__device__ float g_node_agg[NN * DD];        // 25.6 MB
__device__ float g_coord_sum[NN * CC * 3];   // 4.8 MB
__device__ float g_cnt[NN];
__device__ float g_pcol[NN * 3];
__device__ int   g_csum[NN];
__device__ unsigned int g_maxbits;

// K-pair-interleaved packed weights: element [kp*COLS + j] = pack(w[2kp][j], w[2kp+1][j])
__device__ unsigned long long g_W1p[132 * 128];   // m_w1: 264x128
__device__ unsigned long long g_W2p[64 * 128];    // m_w2: 128x128
__device__ unsigned long long g_CW1p[64 * 128];   // c_w1: 128x128
__device__ unsigned long long g_HWp[64 * 128];    // het_w: 128x128
__device__ unsigned long long g_CW2p[64 * 8];     // c_w2: 128x8

__device__ __forceinline__ float silu_f(float x) {
    return x * (1.0f / (1.0f + __expf(-x)));
}

__device__ __forceinline__ unsigned long long packf2(float lo, float hi) {
    return ((unsigned long long)__float_as_uint(hi) << 32) | (unsigned long long)__float_as_uint(lo);
}
__device__ __forceinline__ float lo_f(unsigned long long p) { return __uint_as_float((unsigned)(p & 0xffffffffull)); }
__device__ __forceinline__ float hi_f(unsigned long long p) { return __uint_as_float((unsigned)(p >> 32)); }

#define FMA2(d, a, b, c) asm("fma.rn.f32x2 %0, %1, %2, %3;" : "=l"(d) : "l"(a), "l"(b), "l"(c))

// ---------------- zero scratch ----------------
__global__ void zero_kernel() {
    long t0 = (long)blockIdx.x * blockDim.x + threadIdx.x;
    long stride = (long)gridDim.x * blockDim.x;
    for (long i = t0; i < (long)NN * DD; i += stride) g_node_agg[i] = 0.f;
    for (long i = t0; i < (long)NN * 24; i += stride) g_coord_sum[i] = 0.f;
    for (long i = t0; i < NN; i += stride) g_cnt[i] = 0.f;
    if (t0 == 0) g_maxbits = 0u;
}

// ---------------- weight pre-packing (K-pair interleave) ----------------
__global__ void pack_kernel(const float* __restrict__ m_w1,
                            const float* __restrict__ m_w2,
                            const float* __restrict__ c_w1,
                            const float* __restrict__ c_w2,
                            const float* __restrict__ het_w) {
    int t0 = blockIdx.x * blockDim.x + threadIdx.x;
    int stride = gridDim.x * blockDim.x;
    for (int i = t0; i < 132 * 128; i += stride) {
        int kp = i >> 7, j = i & 127;
        g_W1p[i] = packf2(m_w1[(2 * kp) * 128 + j], m_w1[(2 * kp + 1) * 128 + j]);
    }
    for (int i = t0; i < 64 * 128; i += stride) {
        int kp = i >> 7, j = i & 127;
        g_W2p[i]  = packf2(m_w2[(2 * kp) * 128 + j],  m_w2[(2 * kp + 1) * 128 + j]);
        g_CW1p[i] = packf2(c_w1[(2 * kp) * 128 + j],  c_w1[(2 * kp + 1) * 128 + j]);
        g_HWp[i]  = packf2(het_w[(2 * kp) * 128 + j], het_w[(2 * kp + 1) * 128 + j]);
    }
    for (int i = t0; i < 64 * 8; i += stride) {
        int kp = i >> 3, j = i & 7;
        g_CW2p[i] = packf2(c_w2[(2 * kp) * 8 + j], c_w2[(2 * kp + 1) * 8 + j]);
    }
}

// ---------------- per-node precompute: csum, pooled_col ----------------
__global__ void node_pre_kernel(const float* __restrict__ coords,
                                const float* __restrict__ cw) {
    int n = blockIdx.x * blockDim.x + threadIdx.x;
    if (n >= NN) return;
    float px = 0.f, py = 0.f, pz = 0.f;
    int cs = 0;
#pragma unroll
    for (int c = 0; c < 8; c++) {
        float w = cw[n * 8 + c];
        if (w != 0.f) {
            cs++;
            px += coords[n * 24 + c * 3 + 0];
            py += coords[n * 24 + c * 3 + 1];
            pz += coords[n * 24 + c * 3 + 2];
        }
    }
    float inv = 1.f / ((float)cs + 0.001f);
    g_pcol[n * 3 + 0] = px * inv;
    g_pcol[n * 3 + 1] = py * inv;
    g_pcol[n * 3 + 2] = pz * inv;
    g_csum[n] = cs;
}

// ---------------- global max of squared channel distances ----------------
__global__ void max_kernel(const float* __restrict__ coords,
                           const int* __restrict__ el) {
    int e = blockIdx.x * blockDim.x + threadIdx.x;
    float m = 0.f;
    if (e < EE) {
        int src = el[e * 3 + 0];
        int tgt = el[e * 3 + 1];
        float ct[24], cs[24];
#pragma unroll
        for (int i = 0; i < 24; i++) {
            ct[i] = coords[(long)tgt * 24 + i];
            cs[i] = coords[(long)src * 24 + i];
        }
#pragma unroll
        for (int c = 0; c < 8; c++) {
#pragma unroll
            for (int d = 0; d < 8; d++) {
                float dx = ct[c * 3 + 0] - cs[d * 3 + 0];
                float dy = ct[c * 3 + 1] - cs[d * 3 + 1];
                float dz = ct[c * 3 + 2] - cs[d * 3 + 2];
                float ns = dx * dx + dy * dy + dz * dz;
                m = fmaxf(m, ns);
            }
        }
    }
#pragma unroll
    for (int o = 16; o > 0; o >>= 1)
        m = fmaxf(m, __shfl_xor_sync(0xffffffffu, m, o));
    if ((threadIdx.x & 31) == 0)
        atomicMax(&g_maxbits, __float_as_uint(m));  // valid for non-negative floats
}

// ---------------- fused edge kernel ----------------
struct EdgeSmem {
    float xs[TILE_E * XS];     // x = [h_tgt | h_src | radial] tiles
    float ms1[TILE_E * MS];    // m1 / cf reuse
    float ms2[TILE_E * MS];    // m (post-GEMM2)
    float wscr[16][320];       // per-warp scratch: At(0) Bs(64) M(128) T(192) cwt(256) cws(264) ct(272) cs(296)
    float cdiff[TILE_E * 24];
    float ef[TILE_E * 8];
    int   s_tgt[TILE_E];
    float s_ew[TILE_E];
    float s_wr[TILE_E];
    int   s_ts[TILE_E];
};

// 64 (edges) x 128 (cols) GEMM with packed-K FFMA2.
// 512 threads: eg = tid>>5 (16 groups of 4 edges), cg = lane (32 groups of 4 cols).
template <int KP>
__device__ __forceinline__ void tile_gemm(const float* __restrict__ src, int sstride,
                                          const unsigned long long* __restrict__ Wp,
                                          const float* __restrict__ bias,
                                          float* __restrict__ dst, int tid) {
    const int cg = tid & 31;
    const int eg = tid >> 5;
    unsigned long long acc[4][4];
#pragma unroll
    for (int r = 0; r < 4; r++)
#pragma unroll
        for (int c = 0; c < 4; c++) acc[r][c] = 0ull;

    const ulonglong2* Wv = (const ulonglong2*)Wp;  // [KP][64] of ulonglong2
#pragma unroll 2
    for (int kp = 0; kp < KP; kp++) {
        ulonglong2 wa = Wv[kp * 64 + cg * 2 + 0];  // cols 4cg, 4cg+1
        ulonglong2 wb = Wv[kp * 64 + cg * 2 + 1];  // cols 4cg+2, 4cg+3
#pragma unroll
        for (int r = 0; r < 4; r++) {
            unsigned long long xv = *(const unsigned long long*)&src[(eg * 4 + r) * sstride + kp * 2];
            FMA2(acc[r][0], xv, wa.x, acc[r][0]);
            FMA2(acc[r][1], xv, wa.y, acc[r][1]);
            FMA2(acc[r][2], xv, wb.x, acc[r][2]);
            FMA2(acc[r][3], xv, wb.y, acc[r][3]);
        }
    }
    float4 bb = *(const float4*)&bias[cg * 4];
#pragma unroll
    for (int r = 0; r < 4; r++) {
        float4 o;
        o.x = silu_f(lo_f(acc[r][0]) + hi_f(acc[r][0]) + bb.x);
        o.y = silu_f(lo_f(acc[r][1]) + hi_f(acc[r][1]) + bb.y);
        o.z = silu_f(lo_f(acc[r][2]) + hi_f(acc[r][2]) + bb.z);
        o.w = silu_f(lo_f(acc[r][3]) + hi_f(acc[r][3]) + bb.w);
        *(float4*)&dst[(eg * 4 + r) * MS + cg * 4] = o;
    }
}

__global__ __launch_bounds__(512, 1)
void edge_kernel(const float* __restrict__ h,
                 const float* __restrict__ coords,
                 const float* __restrict__ ca,
                 const float* __restrict__ cw,
                 const float* __restrict__ edge_weights,
                 const int* __restrict__ el,
                 const float* __restrict__ rl_w,
                 const float* __restrict__ rl_b,
                 const float* __restrict__ m_b1,
                 const float* __restrict__ m_b2,
                 const float* __restrict__ c_b1,
                 const float* __restrict__ w_r) {
    extern __shared__ char smem_raw[];
    EdgeSmem& sm = *reinterpret_cast<EdgeSmem*>(smem_raw);

    const int tid = threadIdx.x;
    const int wid = tid >> 5;
    const int lane = tid & 31;
    const long tileBase = (long)blockIdx.x * TILE_E;

    float gmax = sqrtf(__uint_as_float(g_maxbits));
    float inv_g = 1.f / (gmax + 0.001f);

    float* WS  = &sm.wscr[wid][0];
    float* At  = WS;
    float* Bs  = WS + 64;
    float* Mm  = WS + 128;
    float* Tt  = WS + 192;
    float* cwt = WS + 256;
    float* cws = WS + 264;
    float* ctb = WS + 272;
    float* csb = WS + 296;

    // ---- Phase A: per-edge preprocessing (each of 16 warps handles 4 edges) ----
    for (int i = 0; i < 4; i++) {
        int e = wid * 4 + i;
        long ge = tileBase + e;
        bool valid = (ge < (long)EE);
        int src = 0, tgt = 0, rel = 0;
        if (valid) {
            src = el[ge * 3 + 0];
            tgt = el[ge * 3 + 1];
            rel = el[ge * 3 + 2];
        }
        if (lane == 0) {
            sm.s_tgt[e] = valid ? tgt : -1;
            sm.s_ew[e]  = valid ? edge_weights[ge] : 0.f;
            sm.s_wr[e]  = valid ? w_r[rel] : 0.f;
            int cs = valid ? g_csum[tgt] : 1;
            int ts = cs - 1;
            ts = ts < 0 ? 0 : (ts > 7 ? 7 : ts);
            sm.s_ts[e] = ts;
        }
        if (!valid) {
            for (int k = lane; k < 264; k += 32) sm.xs[e * XS + k] = 0.f;
            for (int k = lane; k < 24;  k += 32) sm.cdiff[e * 24 + k] = 0.f;
            __syncwarp();
            continue;
        }
        // stage per-edge operands
        At[lane]      = ca[(long)tgt * 64 + lane];
        At[lane + 32] = ca[(long)tgt * 64 + lane + 32];
        Bs[lane]      = ca[(long)src * 64 + lane];
        Bs[lane + 32] = ca[(long)src * 64 + lane + 32];
        if (lane < 8) { cwt[lane] = cw[(long)tgt * 8 + lane]; cws[lane] = cw[(long)src * 8 + lane]; }
        if (lane < 24) { ctb[lane] = coords[(long)tgt * 24 + lane]; csb[lane] = coords[(long)src * 24 + lane]; }
        __syncwarp();

        // M[c][d] = (||ct_c - cs_d|| / (gmax+eps)) * cwt[c]*cws[d]
#pragma unroll
        for (int half = 0; half < 2; half++) {
            int idx = lane + half * 32;
            int c = idx >> 3, d = idx & 7;
            float dx = ctb[c * 3 + 0] - csb[d * 3 + 0];
            float dy = ctb[c * 3 + 1] - csb[d * 3 + 1];
            float dz = ctb[c * 3 + 2] - csb[d * 3 + 2];
            float ns = dx * dx + dy * dy + dz * dz;
            float nrm = (ns > 0.f) ? ns * rsqrtf(ns) : 0.f;
            Mm[idx] = nrm * inv_g * cwt[c] * cws[d];
        }
        __syncwarp();

        // T[a][d] = sum_c At[c][a] * M[c][d]
#pragma unroll
        for (int half = 0; half < 2; half++) {
            int idx = lane + half * 32;
            int a = idx >> 3, d = idx & 7;
            float t = 0.f;
#pragma unroll
            for (int c = 0; c < 8; c++) t = fmaf(At[c * 8 + a], Mm[c * 8 + d], t);
            Tt[idx] = t;
        }
        __syncwarp();

        // R[a][b] = sum_d T[a][d] * Bs[d][b]
        float r0 = 0.f, r1 = 0.f;
        {
            int a = lane >> 3, b = lane & 7;
#pragma unroll
            for (int d = 0; d < 8; d++) r0 = fmaf(Tt[a * 8 + d], Bs[d * 8 + b], r0);
            int idx = lane + 32;
            a = idx >> 3; b = idx & 7;
#pragma unroll
            for (int d = 0; d < 8; d++) r1 = fmaf(Tt[a * 8 + d], Bs[d * 8 + b], r1);
        }
        float ss = r0 * r0 + r1 * r1;
#pragma unroll
        for (int o = 16; o > 0; o >>= 1) ss += __shfl_xor_sync(0xffffffffu, ss, o);
        float invn = 1.f / (sqrtf(ss) + 0.001f);
        Mm[lane] = r0;           // reuse M as flattened R
        Mm[lane + 32] = r1;
        __syncwarp();

        // radial_out[j] = (R . rl_w[:,j]) * invn + rl_b[j]  -> xs[e][256+j]
        if (lane < 8) {
            float acc = 0.f;
#pragma unroll
            for (int k = 0; k < 64; k++) acc = fmaf(Mm[k], rl_w[k * 8 + lane], acc);
            sm.xs[e * XS + 256 + lane] = acc * invn + rl_b[lane];
        }
        // gather h[tgt], h[src] -> xs[e][0..255]
        ((float4*)&sm.xs[e * XS])[lane]      = ((const float4*)(h + (long)tgt * 128))[lane];
        ((float4*)&sm.xs[e * XS])[lane + 32] = ((const float4*)(h + (long)src * 128))[lane];
        // coord_diff = coords[tgt] - pooled_col[src]
        if (lane < 24) {
            int k = lane % 3;
            sm.cdiff[e * 24 + lane] = ctb[lane] - g_pcol[(long)src * 3 + k];
        }
        __syncwarp();
    }
    __syncthreads();

    // ---- GEMM chain (packed-K FFMA2) ----
    tile_gemm<132>(sm.xs,  XS, g_W1p,  m_b1, sm.ms1, tid);  // m1 = silu(x@W1+b1)
    __syncthreads();
    tile_gemm<64>(sm.ms1, MS, g_W2p,  m_b2, sm.ms2, tid);   // m  = silu(m1@W2+b2)
    __syncthreads();
    tile_gemm<64>(sm.ms2, MS, g_CW1p, c_b1, sm.ms1, tid);   // cf = silu(m@Cw1+Cb1)
    __syncthreads();

    // edge_feat = cf @ c_w2  (64 edges x 8), packed-K
    {
        int e = tid >> 3;
        int j = tid & 7;
        unsigned long long acc = 0ull;
#pragma unroll 8
        for (int kp = 0; kp < 64; kp++) {
            unsigned long long cf = *(const unsigned long long*)&sm.ms1[e * MS + kp * 2];
            FMA2(acc, cf, g_CW2p[kp * 8 + j], acc);
        }
        sm.ef[e * 8 + j] = lo_f(acc) + hi_f(acc);
    }
    __syncthreads();

    // ---- aggregation atomics ----
    // node_agg[tgt] += m * ew
    for (int idx = tid; idx < TILE_E * 128; idx += 512) {
        int e = idx >> 7, j = idx & 127;
        int t = sm.s_tgt[e];
        if (t >= 0)
            atomicAdd(&g_node_agg[(long)t * 128 + j], sm.ms2[e * MS + j] * sm.s_ew[e]);
    }
    // coord_sum[tgt] += w_r * coord_diff * pooled_edge
    for (int idx = tid; idx < TILE_E * 8; idx += 512) {
        int e = idx >> 3, a = idx & 7;
        int t = sm.s_tgt[e];
        if (t < 0) continue;
        int ts = sm.s_ts[e];
        int w = 8 - ts;
        int hi = a + w; if (hi > 8) hi = 8;
        float s = 0.f;
        for (int b = a; b < hi; b++) s += sm.ef[e * 8 + b];
        float pe = (s / (float)w) * sm.s_wr[e];
#pragma unroll
        for (int k = 0; k < 3; k++)
            atomicAdd(&g_coord_sum[(long)t * 24 + a * 3 + k], sm.cdiff[e * 24 + a * 3 + k] * pe);
    }
    // cnt[tgt] += 1
    if (tid < TILE_E) {
        int t = sm.s_tgt[tid];
        if (t >= 0) atomicAdd(&g_cnt[t], 1.f);
    }
}

// ---------------- node epilogue: out GEMM + BN + silu + residuals ----------------
__global__ __launch_bounds__(512, 1)
void node_out_kernel(const float* __restrict__ h,
                     const float* __restrict__ coords,
                     const float* __restrict__ het_b,
                     const float* __restrict__ gamma,
                     const float* __restrict__ beta,
                     float* __restrict__ out) {
    __shared__ float ag[64 * MS];
    const int tid = threadIdx.x;
    const int base = blockIdx.x * 64;
    const float INVS = 0.9999950000374996f;  // 1/sqrt(1+1e-5)

    for (int idx = tid; idx < 64 * 128; idx += 512) {
        int n = idx >> 7, k = idx & 127;
        int gn = base + n;
        ag[n * MS + k] = (gn < NN) ? g_node_agg[(long)gn * 128 + k] : 0.f;
    }
    __syncthreads();

    const int cg = tid & 31;
    const int ng = tid >> 5;
    unsigned long long acc[4][4];
#pragma unroll
    for (int r = 0; r < 4; r++)
#pragma unroll
        for (int c = 0; c < 4; c++) acc[r][c] = 0ull;
    const ulonglong2* Wv = (const ulonglong2*)g_HWp;
#pragma unroll 2
    for (int kp = 0; kp < 64; kp++) {
        ulonglong2 wa = Wv[kp * 64 + cg * 2 + 0];
        ulonglong2 wb = Wv[kp * 64 + cg * 2 + 1];
#pragma unroll
        for (int r = 0; r < 4; r++) {
            unsigned long long xv = *(const unsigned long long*)&ag[(ng * 4 + r) * MS + kp * 2];
            FMA2(acc[r][0], xv, wa.x, acc[r][0]);
            FMA2(acc[r][1], xv, wa.y, acc[r][1]);
            FMA2(acc[r][2], xv, wb.x, acc[r][2]);
            FMA2(acc[r][3], xv, wb.y, acc[r][3]);
        }
    }
    int j0 = cg * 4;
    float4 hb = *(const float4*)&het_b[j0];
    float4 gm = *(const float4*)&gamma[j0];
    float4 bt = *(const float4*)&beta[j0];
#pragma unroll
    for (int r = 0; r < 4; r++) {
        int gn = base + ng * 4 + r;
        if (gn < NN) {
            float4 o;
            o.x = silu_f((lo_f(acc[r][0]) + hi_f(acc[r][0]) + hb.x) * INVS * gm.x + bt.x);
            o.y = silu_f((lo_f(acc[r][1]) + hi_f(acc[r][1]) + hb.y) * INVS * gm.y + bt.y);
            o.z = silu_f((lo_f(acc[r][2]) + hi_f(acc[r][2]) + hb.z) * INVS * gm.z + bt.z);
            o.w = silu_f((lo_f(acc[r][3]) + hi_f(acc[r][3]) + hb.w) * INVS * gm.w + bt.w);
            float4 hv = *(const float4*)&h[(long)gn * 128 + j0];
            o.x += hv.x; o.y += hv.y; o.z += hv.z; o.w += hv.w;
            *(float4*)&out[(long)gn * 128 + j0] = o;
        }
    }

    // coord_output = coords + coord_sum / max(cnt,1)
    for (int idx = tid; idx < 64 * 24; idx += 512) {
        int n = idx / 24, k = idx % 24;
        int gn = base + n;
        if (gn < NN) {
            float c = fmaxf(g_cnt[gn], 1.f);
            out[(long)NN * 128 + (long)gn * 24 + k] =
                coords[(long)gn * 24 + k] + g_coord_sum[(long)gn * 24 + k] / c;
        }
    }
}

// ---------------- launch ----------------
extern "C" void kernel_launch(void* const* d_in, const int* in_sizes, int n_in,
                              void* d_out, int out_size) {
    (void)in_sizes; (void)n_in; (void)out_size;
    const float* h      = (const float*)d_in[0];
    const float* coords = (const float*)d_in[1];
    const float* ca     = (const float*)d_in[2];
    const float* cw     = (const float*)d_in[3];
    const float* ew     = (const float*)d_in[4];
    const int*   el     = (const int*)d_in[5];
    const float* rl_w   = (const float*)d_in[6];
    const float* rl_b   = (const float*)d_in[7];
    const float* m_w1   = (const float*)d_in[8];
    const float* m_b1   = (const float*)d_in[9];
    const float* m_w2   = (const float*)d_in[10];
    const float* m_b2   = (const float*)d_in[11];
    const float* c_w1   = (const float*)d_in[12];
    const float* c_b1   = (const float*)d_in[13];
    const float* c_w2   = (const float*)d_in[14];
    const float* het_w  = (const float*)d_in[15];
    const float* het_b  = (const float*)d_in[16];
    const float* gamma  = (const float*)d_in[17];
    const float* beta   = (const float*)d_in[18];
    const float* w_r    = (const float*)d_in[19];
    float* out = (float*)d_out;

    cudaFuncSetAttribute(edge_kernel, cudaFuncAttributeMaxDynamicSharedMemorySize,
                         (int)sizeof(EdgeSmem));

    zero_kernel<<<2048, 256>>>();
    pack_kernel<<<132, 256>>>(m_w1, m_w2, c_w1, c_w2, het_w);
    node_pre_kernel<<<(NN + 255) / 256, 256>>>(coords, cw);
    max_kernel<<<(EE + 255) / 256, 256>>>(coords, el);
    edge_kernel<<<(EE + TILE_E - 1) / TILE_E, 512, sizeof(EdgeSmem)>>>(
        h, coords, ca, cw, ew, el, rl_w, rl_b,
        m_b1, m_b2, c_b1, w_r);
    node_out_kernel<<<(NN + 63) / 64, 512>>>(h, coords, het_b, gamma, beta, out);
}

// round 3
// speedup vs baseline: 1.3584x; 1.2274x over previous
#include <cuda_runtime.h>
#include <math.h>

#define NN 50000
#define EE 400000
#define DD 128
#define CC 8

#define TILE_E 64
#define XS 268   // xs row stride in floats (264 used, 8B-aligned rows)
#define MS 132   // intermediate row stride (128 used, 8B-aligned rows)

// ---------------- device scratch (no allocations allowed) ----------------
__device__ float g_node_agg[NN * DD];        // 25.6 MB
__device__ float g_coord_sum[NN * CC * 3];   // 4.8 MB
__device__ float g_cnt[NN];
__device__ float g_pcol[NN * 3];
__device__ int   g_csum[NN];
__device__ unsigned int g_maxbits;

// K-pair-interleaved packed weights: element [kp*COLS + j] = pack(w[2kp][j], w[2kp+1][j])
__device__ unsigned long long g_W1p[132 * 128];   // m_w1: 264x128
__device__ unsigned long long g_W2p[64 * 128];    // m_w2: 128x128
__device__ unsigned long long g_CW1p[64 * 128];   // c_w1: 128x128
__device__ unsigned long long g_HWp[64 * 128];    // het_w: 128x128
__device__ unsigned long long g_CW2p[64 * 8];     // c_w2: 128x8

__device__ __forceinline__ float silu_f(float x) {
    return x * (1.0f / (1.0f + __expf(-x)));
}

__device__ __forceinline__ unsigned long long packf2(float lo, float hi) {
    return ((unsigned long long)__float_as_uint(hi) << 32) | (unsigned long long)__float_as_uint(lo);
}
__device__ __forceinline__ float lo_f(unsigned long long p) { return __uint_as_float((unsigned)(p & 0xffffffffull)); }
__device__ __forceinline__ float hi_f(unsigned long long p) { return __uint_as_float((unsigned)(p >> 32)); }

#define FMA2(d, a, b, c) asm("fma.rn.f32x2 %0, %1, %2, %3;" : "=l"(d) : "l"(a), "l"(b), "l"(c))

// ---------------- zero scratch ----------------
__global__ void zero_kernel() {
    long t0 = (long)blockIdx.x * blockDim.x + threadIdx.x;
    long stride = (long)gridDim.x * blockDim.x;
    for (long i = t0; i < (long)NN * DD; i += stride) g_node_agg[i] = 0.f;
    for (long i = t0; i < (long)NN * 24; i += stride) g_coord_sum[i] = 0.f;
    for (long i = t0; i < NN; i += stride) g_cnt[i] = 0.f;
    if (t0 == 0) g_maxbits = 0u;
}

// ---------------- weight pre-packing (K-pair interleave) ----------------
__global__ void pack_kernel(const float* __restrict__ m_w1,
                            const float* __restrict__ m_w2,
                            const float* __restrict__ c_w1,
                            const float* __restrict__ c_w2,
                            const float* __restrict__ het_w) {
    int t0 = blockIdx.x * blockDim.x + threadIdx.x;
    int stride = gridDim.x * blockDim.x;
    for (int i = t0; i < 132 * 128; i += stride) {
        int kp = i >> 7, j = i & 127;
        g_W1p[i] = packf2(m_w1[(2 * kp) * 128 + j], m_w1[(2 * kp + 1) * 128 + j]);
    }
    for (int i = t0; i < 64 * 128; i += stride) {
        int kp = i >> 7, j = i & 127;
        g_W2p[i]  = packf2(m_w2[(2 * kp) * 128 + j],  m_w2[(2 * kp + 1) * 128 + j]);
        g_CW1p[i] = packf2(c_w1[(2 * kp) * 128 + j],  c_w1[(2 * kp + 1) * 128 + j]);
        g_HWp[i]  = packf2(het_w[(2 * kp) * 128 + j], het_w[(2 * kp + 1) * 128 + j]);
    }
    for (int i = t0; i < 64 * 8; i += stride) {
        int kp = i >> 3, j = i & 7;
        g_CW2p[i] = packf2(c_w2[(2 * kp) * 8 + j], c_w2[(2 * kp + 1) * 8 + j]);
    }
}

// ---------------- per-node precompute: csum, pooled_col ----------------
__global__ void node_pre_kernel(const float* __restrict__ coords,
                                const float* __restrict__ cw) {
    int n = blockIdx.x * blockDim.x + threadIdx.x;
    if (n >= NN) return;
    float px = 0.f, py = 0.f, pz = 0.f;
    int cs = 0;
#pragma unroll
    for (int c = 0; c < 8; c++) {
        float w = cw[n * 8 + c];
        if (w != 0.f) {
            cs++;
            px += coords[n * 24 + c * 3 + 0];
            py += coords[n * 24 + c * 3 + 1];
            pz += coords[n * 24 + c * 3 + 2];
        }
    }
    float inv = 1.f / ((float)cs + 0.001f);
    g_pcol[n * 3 + 0] = px * inv;
    g_pcol[n * 3 + 1] = py * inv;
    g_pcol[n * 3 + 2] = pz * inv;
    g_csum[n] = cs;
}

// ---------------- global max of squared channel distances ----------------
__global__ void max_kernel(const float* __restrict__ coords,
                           const int* __restrict__ el) {
    int e = blockIdx.x * blockDim.x + threadIdx.x;
    float m = 0.f;
    if (e < EE) {
        int src = el[e * 3 + 0];
        int tgt = el[e * 3 + 1];
        float ct[24], cs[24];
#pragma unroll
        for (int i = 0; i < 24; i++) {
            ct[i] = coords[(long)tgt * 24 + i];
            cs[i] = coords[(long)src * 24 + i];
        }
#pragma unroll
        for (int c = 0; c < 8; c++) {
#pragma unroll
            for (int d = 0; d < 8; d++) {
                float dx = ct[c * 3 + 0] - cs[d * 3 + 0];
                float dy = ct[c * 3 + 1] - cs[d * 3 + 1];
                float dz = ct[c * 3 + 2] - cs[d * 3 + 2];
                float ns = dx * dx + dy * dy + dz * dz;
                m = fmaxf(m, ns);
            }
        }
    }
#pragma unroll
    for (int o = 16; o > 0; o >>= 1)
        m = fmaxf(m, __shfl_xor_sync(0xffffffffu, m, o));
    if ((threadIdx.x & 31) == 0)
        atomicMax(&g_maxbits, __float_as_uint(m));  // valid for non-negative floats
}

// ---------------- fused edge kernel ----------------
struct EdgeSmem {
    float xs[TILE_E * XS];     // x = [h_tgt | h_src | radial] tiles
    float ms1[TILE_E * MS];    // m1 / cf reuse
    float ms2[TILE_E * MS];    // m (post-GEMM2)
    float wscr[16][320];       // per-warp scratch: At(0) Bs(64) M(128) T(192) cwt(256) cws(264) ct(272) cs(296)
    float cdiff[TILE_E * 24];
    float ef[TILE_E * 8];
    int   s_tgt[TILE_E];
    float s_ew[TILE_E];
    float s_wr[TILE_E];
    int   s_ts[TILE_E];
};

// 64 (edges) x 128 (cols) GEMM with packed-K FFMA2.
// 512 threads: eg = tid>>6 (8 groups of 8 edges), cg = tid&63 (64 groups of 2 cols).
// Per kp each thread loads ONE ulonglong2 of weights (16B) and reuses it over
// 8 edge rows -> 2 FMA/weight-byte, halving L1tex weight wavefront traffic.
template <int KP>
__device__ __forceinline__ void tile_gemm(const float* __restrict__ src, int sstride,
                                          const unsigned long long* __restrict__ Wp,
                                          const float* __restrict__ bias,
                                          float* __restrict__ dst, int tid) {
    const int cg = tid & 63;
    const int eg = tid >> 6;
    unsigned long long acc0[8], acc1[8];
#pragma unroll
    for (int r = 0; r < 8; r++) { acc0[r] = 0ull; acc1[r] = 0ull; }

    const ulonglong2* Wv = (const ulonglong2*)Wp;  // [KP][64] of ulonglong2
    const float* srow = &src[eg * 8 * sstride];
#pragma unroll 4
    for (int kp = 0; kp < KP; kp++) {
        ulonglong2 w = Wv[kp * 64 + cg];           // cols 2cg, 2cg+1
#pragma unroll
        for (int r = 0; r < 8; r++) {
            unsigned long long xv = *(const unsigned long long*)&srow[r * sstride + kp * 2];
            FMA2(acc0[r], xv, w.x, acc0[r]);
            FMA2(acc1[r], xv, w.y, acc1[r]);
        }
    }
    float2 bb = *(const float2*)&bias[cg * 2];
#pragma unroll
    for (int r = 0; r < 8; r++) {
        float2 o;
        o.x = silu_f(lo_f(acc0[r]) + hi_f(acc0[r]) + bb.x);
        o.y = silu_f(lo_f(acc1[r]) + hi_f(acc1[r]) + bb.y);
        *(float2*)&dst[(eg * 8 + r) * MS + cg * 2] = o;
    }
}

__global__ __launch_bounds__(512, 1)
void edge_kernel(const float* __restrict__ h,
                 const float* __restrict__ coords,
                 const float* __restrict__ ca,
                 const float* __restrict__ cw,
                 const float* __restrict__ edge_weights,
                 const int* __restrict__ el,
                 const float* __restrict__ rl_w,
                 const float* __restrict__ rl_b,
                 const float* __restrict__ m_b1,
                 const float* __restrict__ m_b2,
                 const float* __restrict__ c_b1,
                 const float* __restrict__ w_r) {
    extern __shared__ char smem_raw[];
    EdgeSmem& sm = *reinterpret_cast<EdgeSmem*>(smem_raw);

    const int tid = threadIdx.x;
    const int wid = tid >> 5;
    const int lane = tid & 31;
    const long tileBase = (long)blockIdx.x * TILE_E;

    float gmax = sqrtf(__uint_as_float(g_maxbits));
    float inv_g = 1.f / (gmax + 0.001f);

    float* WS  = &sm.wscr[wid][0];
    float* At  = WS;
    float* Bs  = WS + 64;
    float* Mm  = WS + 128;
    float* Tt  = WS + 192;
    float* cwt = WS + 256;
    float* cws = WS + 264;
    float* ctb = WS + 272;
    float* csb = WS + 296;

    // ---- Phase A: per-edge preprocessing (each of 16 warps handles 4 edges) ----
    for (int i = 0; i < 4; i++) {
        int e = wid * 4 + i;
        long ge = tileBase + e;
        bool valid = (ge < (long)EE);
        int src = 0, tgt = 0, rel = 0;
        if (valid) {
            src = el[ge * 3 + 0];
            tgt = el[ge * 3 + 1];
            rel = el[ge * 3 + 2];
        }
        if (lane == 0) {
            sm.s_tgt[e] = valid ? tgt : -1;
            sm.s_ew[e]  = valid ? edge_weights[ge] : 0.f;
            sm.s_wr[e]  = valid ? w_r[rel] : 0.f;
            int cs = valid ? g_csum[tgt] : 1;
            int ts = cs - 1;
            ts = ts < 0 ? 0 : (ts > 7 ? 7 : ts);
            sm.s_ts[e] = ts;
        }
        if (!valid) {
            for (int k = lane; k < 264; k += 32) sm.xs[e * XS + k] = 0.f;
            for (int k = lane; k < 24;  k += 32) sm.cdiff[e * 24 + k] = 0.f;
            __syncwarp();
            continue;
        }
        // stage per-edge operands
        At[lane]      = ca[(long)tgt * 64 + lane];
        At[lane + 32] = ca[(long)tgt * 64 + lane + 32];
        Bs[lane]      = ca[(long)src * 64 + lane];
        Bs[lane + 32] = ca[(long)src * 64 + lane + 32];
        if (lane < 8) { cwt[lane] = cw[(long)tgt * 8 + lane]; cws[lane] = cw[(long)src * 8 + lane]; }
        if (lane < 24) { ctb[lane] = coords[(long)tgt * 24 + lane]; csb[lane] = coords[(long)src * 24 + lane]; }
        __syncwarp();

        // M[c][d] = (||ct_c - cs_d|| / (gmax+eps)) * cwt[c]*cws[d]
#pragma unroll
        for (int half = 0; half < 2; half++) {
            int idx = lane + half * 32;
            int c = idx >> 3, d = idx & 7;
            float dx = ctb[c * 3 + 0] - csb[d * 3 + 0];
            float dy = ctb[c * 3 + 1] - csb[d * 3 + 1];
            float dz = ctb[c * 3 + 2] - csb[d * 3 + 2];
            float ns = dx * dx + dy * dy + dz * dz;
            float nrm = (ns > 0.f) ? ns * rsqrtf(ns) : 0.f;
            Mm[idx] = nrm * inv_g * cwt[c] * cws[d];
        }
        __syncwarp();

        // T[a][d] = sum_c At[c][a] * M[c][d]
#pragma unroll
        for (int half = 0; half < 2; half++) {
            int idx = lane + half * 32;
            int a = idx >> 3, d = idx & 7;
            float t = 0.f;
#pragma unroll
            for (int c = 0; c < 8; c++) t = fmaf(At[c * 8 + a], Mm[c * 8 + d], t);
            Tt[idx] = t;
        }
        __syncwarp();

        // R[a][b] = sum_d T[a][d] * Bs[d][b]
        float r0 = 0.f, r1 = 0.f;
        {
            int a = lane >> 3, b = lane & 7;
#pragma unroll
            for (int d = 0; d < 8; d++) r0 = fmaf(Tt[a * 8 + d], Bs[d * 8 + b], r0);
            int idx = lane + 32;
            a = idx >> 3; b = idx & 7;
#pragma unroll
            for (int d = 0; d < 8; d++) r1 = fmaf(Tt[a * 8 + d], Bs[d * 8 + b], r1);
        }
        float ss = r0 * r0 + r1 * r1;
#pragma unroll
        for (int o = 16; o > 0; o >>= 1) ss += __shfl_xor_sync(0xffffffffu, ss, o);
        float invn = 1.f / (sqrtf(ss) + 0.001f);
        Mm[lane] = r0;           // reuse M as flattened R
        Mm[lane + 32] = r1;
        __syncwarp();

        // radial_out[j] = (R . rl_w[:,j]) * invn + rl_b[j]  -> xs[e][256+j]
        if (lane < 8) {
            float acc = 0.f;
#pragma unroll
            for (int k = 0; k < 64; k++) acc = fmaf(Mm[k], rl_w[k * 8 + lane], acc);
            sm.xs[e * XS + 256 + lane] = acc * invn + rl_b[lane];
        }
        // gather h[tgt], h[src] -> xs[e][0..255]
        ((float4*)&sm.xs[e * XS])[lane]      = ((const float4*)(h + (long)tgt * 128))[lane];
        ((float4*)&sm.xs[e * XS])[lane + 32] = ((const float4*)(h + (long)src * 128))[lane];
        // coord_diff = coords[tgt] - pooled_col[src]
        if (lane < 24) {
            int k = lane % 3;
            sm.cdiff[e * 24 + lane] = ctb[lane] - g_pcol[(long)src * 3 + k];
        }
        __syncwarp();
    }
    __syncthreads();

    // ---- GEMM chain (packed-K FFMA2, 8 rows x 2 cols per thread) ----
    tile_gemm<132>(sm.xs,  XS, g_W1p,  m_b1, sm.ms1, tid);  // m1 = silu(x@W1+b1)
    __syncthreads();
    tile_gemm<64>(sm.ms1, MS, g_W2p,  m_b2, sm.ms2, tid);   // m  = silu(m1@W2+b2)
    __syncthreads();
    tile_gemm<64>(sm.ms2, MS, g_CW1p, c_b1, sm.ms1, tid);   // cf = silu(m@Cw1+Cb1)
    __syncthreads();

    // edge_feat = cf @ c_w2  (64 edges x 8), packed-K
    {
        int e = tid >> 3;
        int j = tid & 7;
        unsigned long long acc = 0ull;
#pragma unroll 8
        for (int kp = 0; kp < 64; kp++) {
            unsigned long long cf = *(const unsigned long long*)&sm.ms1[e * MS + kp * 2];
            FMA2(acc, cf, g_CW2p[kp * 8 + j], acc);
        }
        sm.ef[e * 8 + j] = lo_f(acc) + hi_f(acc);
    }
    __syncthreads();

    // ---- aggregation atomics ----
    // node_agg[tgt] += m * ew
    for (int idx = tid; idx < TILE_E * 128; idx += 512) {
        int e = idx >> 7, j = idx & 127;
        int t = sm.s_tgt[e];
        if (t >= 0)
            atomicAdd(&g_node_agg[(long)t * 128 + j], sm.ms2[e * MS + j] * sm.s_ew[e]);
    }
    // coord_sum[tgt] += w_r * coord_diff * pooled_edge
    for (int idx = tid; idx < TILE_E * 8; idx += 512) {
        int e = idx >> 3, a = idx & 7;
        int t = sm.s_tgt[e];
        if (t < 0) continue;
        int ts = sm.s_ts[e];
        int w = 8 - ts;
        int hi = a + w; if (hi > 8) hi = 8;
        float s = 0.f;
        for (int b = a; b < hi; b++) s += sm.ef[e * 8 + b];
        float pe = (s / (float)w) * sm.s_wr[e];
#pragma unroll
        for (int k = 0; k < 3; k++)
            atomicAdd(&g_coord_sum[(long)t * 24 + a * 3 + k], sm.cdiff[e * 24 + a * 3 + k] * pe);
    }
    // cnt[tgt] += 1
    if (tid < TILE_E) {
        int t = sm.s_tgt[tid];
        if (t >= 0) atomicAdd(&g_cnt[t], 1.f);
    }
}

// ---------------- node epilogue: out GEMM + BN + silu + residuals ----------------
__global__ __launch_bounds__(512, 1)
void node_out_kernel(const float* __restrict__ h,
                     const float* __restrict__ coords,
                     const float* __restrict__ het_b,
                     const float* __restrict__ gamma,
                     const float* __restrict__ beta,
                     float* __restrict__ out) {
    __shared__ float ag[64 * MS];
    const int tid = threadIdx.x;
    const int base = blockIdx.x * 64;
    const float INVS = 0.9999950000374996f;  // 1/sqrt(1+1e-5)

    for (int idx = tid; idx < 64 * 128; idx += 512) {
        int n = idx >> 7, k = idx & 127;
        int gn = base + n;
        ag[n * MS + k] = (gn < NN) ? g_node_agg[(long)gn * 128 + k] : 0.f;
    }
    __syncthreads();

    const int cg = tid & 63;
    const int ng = tid >> 6;
    unsigned long long acc0[8], acc1[8];
#pragma unroll
    for (int r = 0; r < 8; r++) { acc0[r] = 0ull; acc1[r] = 0ull; }
    const ulonglong2* Wv = (const ulonglong2*)g_HWp;
#pragma unroll 4
    for (int kp = 0; kp < 64; kp++) {
        ulonglong2 w = Wv[kp * 64 + cg];
#pragma unroll
        for (int r = 0; r < 8; r++) {
            unsigned long long xv = *(const unsigned long long*)&ag[(ng * 8 + r) * MS + kp * 2];
            FMA2(acc0[r], xv, w.x, acc0[r]);
            FMA2(acc1[r], xv, w.y, acc1[r]);
        }
    }
    int j0 = cg * 2;
    float2 hb = *(const float2*)&het_b[j0];
    float2 gm = *(const float2*)&gamma[j0];
    float2 bt = *(const float2*)&beta[j0];
#pragma unroll
    for (int r = 0; r < 8; r++) {
        int gn = base + ng * 8 + r;
        if (gn < NN) {
            float2 o;
            o.x = silu_f((lo_f(acc0[r]) + hi_f(acc0[r]) + hb.x) * INVS * gm.x + bt.x);
            o.y = silu_f((lo_f(acc1[r]) + hi_f(acc1[r]) + hb.y) * INVS * gm.y + bt.y);
            float2 hv = *(const float2*)&h[(long)gn * 128 + j0];
            o.x += hv.x; o.y += hv.y;
            *(float2*)&out[(long)gn * 128 + j0] = o;
        }
    }

    // coord_output = coords + coord_sum / max(cnt,1)
    for (int idx = tid; idx < 64 * 24; idx += 512) {
        int n = idx / 24, k = idx % 24;
        int gn = base + n;
        if (gn < NN) {
            float c = fmaxf(g_cnt[gn], 1.f);
            out[(long)NN * 128 + (long)gn * 24 + k] =
                coords[(long)gn * 24 + k] + g_coord_sum[(long)gn * 24 + k] / c;
        }
    }
}

// ---------------- launch ----------------
extern "C" void kernel_launch(void* const* d_in, const int* in_sizes, int n_in,
                              void* d_out, int out_size) {
    (void)in_sizes; (void)n_in; (void)out_size;
    const float* h      = (const float*)d_in[0];
    const float* coords = (const float*)d_in[1];
    const float* ca     = (const float*)d_in[2];
    const float* cw     = (const float*)d_in[3];
    const float* ew     = (const float*)d_in[4];
    const int*   el     = (const int*)d_in[5];
    const float* rl_w   = (const float*)d_in[6];
    const float* rl_b   = (const float*)d_in[7];
    const float* m_w1   = (const float*)d_in[8];
    const float* m_b1   = (const float*)d_in[9];
    const float* m_w2   = (const float*)d_in[10];
    const float* m_b2   = (const float*)d_in[11];
    const float* c_w1   = (const float*)d_in[12];
    const float* c_b1   = (const float*)d_in[13];
    const float* c_w2   = (const float*)d_in[14];
    const float* het_w  = (const float*)d_in[15];
    const float* het_b  = (const float*)d_in[16];
    const float* gamma  = (const float*)d_in[17];
    const float* beta   = (const float*)d_in[18];
    const float* w_r    = (const float*)d_in[19];
    float* out = (float*)d_out;

    cudaFuncSetAttribute(edge_kernel, cudaFuncAttributeMaxDynamicSharedMemorySize,
                         (int)sizeof(EdgeSmem));

    zero_kernel<<<2048, 256>>>();
    pack_kernel<<<132, 256>>>(m_w1, m_w2, c_w1, c_w2, het_w);
    node_pre_kernel<<<(NN + 255) / 256, 256>>>(coords, cw);
    max_kernel<<<(EE + 255) / 256, 256>>>(coords, el);
    edge_kernel<<<(EE + TILE_E - 1) / TILE_E, 512, sizeof(EdgeSmem)>>>(
        h, coords, ca, cw, ew, el, rl_w, rl_b,
        m_b1, m_b2, c_b1, w_r);
    node_out_kernel<<<(NN + 63) / 64, 512>>>(h, coords, het_b, gamma, beta, out);
}

// round 4
// speedup vs baseline: 1.4426x; 1.0620x over previous
#include <cuda_runtime.h>
#include <math.h>

#define NN 50000
#define EE 400000
#define DD 128
#define CC 8

#define TILE_E 32
#define NTHR 256
#define XS 268   // xs row stride in floats (264 used, 8B-aligned rows)
#define MS 132   // intermediate row stride (128 used, 8B-aligned rows)

// ---------------- device scratch (no allocations allowed) ----------------
__device__ float g_node_agg[NN * DD];        // 25.6 MB
__device__ float g_coord_sum[NN * CC * 3];   // 4.8 MB
__device__ float g_cnt[NN];
__device__ float g_pcol[NN * 3];
__device__ int   g_csum[NN];
__device__ unsigned int g_maxbits;

// K-pair-interleaved packed weights: element [kp*COLS + j] = pack(w[2kp][j], w[2kp+1][j])
__device__ unsigned long long g_W1p[132 * 128];   // m_w1: 264x128
__device__ unsigned long long g_W2p[64 * 128];    // m_w2: 128x128
__device__ unsigned long long g_CW1p[64 * 128];   // c_w1: 128x128
__device__ unsigned long long g_HWp[64 * 128];    // het_w: 128x128
__device__ unsigned long long g_CW2p[64 * 8];     // c_w2: 128x8

__device__ __forceinline__ float silu_f(float x) {
    return x * (1.0f / (1.0f + __expf(-x)));
}

__device__ __forceinline__ unsigned long long packf2(float lo, float hi) {
    return ((unsigned long long)__float_as_uint(hi) << 32) | (unsigned long long)__float_as_uint(lo);
}
__device__ __forceinline__ float lo_f(unsigned long long p) { return __uint_as_float((unsigned)(p & 0xffffffffull)); }
__device__ __forceinline__ float hi_f(unsigned long long p) { return __uint_as_float((unsigned)(p >> 32)); }

#define FMA2(d, a, b, c) asm("fma.rn.f32x2 %0, %1, %2, %3;" : "=l"(d) : "l"(a), "l"(b), "l"(c))

// ---------------- zero scratch ----------------
__global__ void zero_kernel() {
    long t0 = (long)blockIdx.x * blockDim.x + threadIdx.x;
    long stride = (long)gridDim.x * blockDim.x;
    for (long i = t0; i < (long)NN * DD; i += stride) g_node_agg[i] = 0.f;
    for (long i = t0; i < (long)NN * 24; i += stride) g_coord_sum[i] = 0.f;
    for (long i = t0; i < NN; i += stride) g_cnt[i] = 0.f;
    if (t0 == 0) g_maxbits = 0u;
}

// ---------------- weight pre-packing (K-pair interleave) ----------------
__global__ void pack_kernel(const float* __restrict__ m_w1,
                            const float* __restrict__ m_w2,
                            const float* __restrict__ c_w1,
                            const float* __restrict__ c_w2,
                            const float* __restrict__ het_w) {
    int t0 = blockIdx.x * blockDim.x + threadIdx.x;
    int stride = gridDim.x * blockDim.x;
    for (int i = t0; i < 132 * 128; i += stride) {
        int kp = i >> 7, j = i & 127;
        g_W1p[i] = packf2(m_w1[(2 * kp) * 128 + j], m_w1[(2 * kp + 1) * 128 + j]);
    }
    for (int i = t0; i < 64 * 128; i += stride) {
        int kp = i >> 7, j = i & 127;
        g_W2p[i]  = packf2(m_w2[(2 * kp) * 128 + j],  m_w2[(2 * kp + 1) * 128 + j]);
        g_CW1p[i] = packf2(c_w1[(2 * kp) * 128 + j],  c_w1[(2 * kp + 1) * 128 + j]);
        g_HWp[i]  = packf2(het_w[(2 * kp) * 128 + j], het_w[(2 * kp + 1) * 128 + j]);
    }
    for (int i = t0; i < 64 * 8; i += stride) {
        int kp = i >> 3, j = i & 7;
        g_CW2p[i] = packf2(c_w2[(2 * kp) * 8 + j], c_w2[(2 * kp + 1) * 8 + j]);
    }
}

// ---------------- per-node precompute: csum, pooled_col ----------------
__global__ void node_pre_kernel(const float* __restrict__ coords,
                                const float* __restrict__ cw) {
    int n = blockIdx.x * blockDim.x + threadIdx.x;
    if (n >= NN) return;
    float px = 0.f, py = 0.f, pz = 0.f;
    int cs = 0;
#pragma unroll
    for (int c = 0; c < 8; c++) {
        float w = cw[n * 8 + c];
        if (w != 0.f) {
            cs++;
            px += coords[n * 24 + c * 3 + 0];
            py += coords[n * 24 + c * 3 + 1];
            pz += coords[n * 24 + c * 3 + 2];
        }
    }
    float inv = 1.f / ((float)cs + 0.001f);
    g_pcol[n * 3 + 0] = px * inv;
    g_pcol[n * 3 + 1] = py * inv;
    g_pcol[n * 3 + 2] = pz * inv;
    g_csum[n] = cs;
}

// ---------------- global max of squared channel distances ----------------
__global__ void max_kernel(const float* __restrict__ coords,
                           const int* __restrict__ el) {
    int e = blockIdx.x * blockDim.x + threadIdx.x;
    float m = 0.f;
    if (e < EE) {
        int src = el[e * 3 + 0];
        int tgt = el[e * 3 + 1];
        float ct[24], cs[24];
#pragma unroll
        for (int i = 0; i < 24; i++) {
            ct[i] = coords[(long)tgt * 24 + i];
            cs[i] = coords[(long)src * 24 + i];
        }
#pragma unroll
        for (int c = 0; c < 8; c++) {
#pragma unroll
            for (int d = 0; d < 8; d++) {
                float dx = ct[c * 3 + 0] - cs[d * 3 + 0];
                float dy = ct[c * 3 + 1] - cs[d * 3 + 1];
                float dz = ct[c * 3 + 2] - cs[d * 3 + 2];
                float ns = dx * dx + dy * dy + dz * dz;
                m = fmaxf(m, ns);
            }
        }
    }
#pragma unroll
    for (int o = 16; o > 0; o >>= 1)
        m = fmaxf(m, __shfl_xor_sync(0xffffffffu, m, o));
    if ((threadIdx.x & 31) == 0)
        atomicMax(&g_maxbits, __float_as_uint(m));  // valid for non-negative floats
}

// ---------------- fused edge kernel ----------------
struct EdgeSmem {
    float xs[TILE_E * XS];     // x = [h_tgt | h_src | radial] tiles
    float ms1[TILE_E * MS];    // m1 / cf reuse
    float ms2[TILE_E * MS];    // m (post-GEMM2)
    float wscr[8][320];        // per-warp scratch: At(0) Bs(64) M(128) T(192) cwt(256) cws(264) ct(272) cs(296)
    float cdiff[TILE_E * 24];
    float ef[TILE_E * 8];
    int   s_tgt[TILE_E];
    float s_ew[TILE_E];
    float s_wr[TILE_E];
    int   s_ts[TILE_E];
};

// 32 (edges) x 128 (cols) GEMM with packed-K FFMA2.
// 256 threads: eg = tid>>6 (4 groups of 8 edges), cg = tid&63 (64 groups of 2 cols).
// Per kp each thread loads ONE ulonglong2 of weights (16B) reused over 8 edge
// rows -> 2 FMA/weight-byte.
template <int KP>
__device__ __forceinline__ void tile_gemm(const float* __restrict__ src, int sstride,
                                          const unsigned long long* __restrict__ Wp,
                                          const float* __restrict__ bias,
                                          float* __restrict__ dst, int tid) {
    const int cg = tid & 63;
    const int eg = tid >> 6;
    unsigned long long acc0[8], acc1[8];
#pragma unroll
    for (int r = 0; r < 8; r++) { acc0[r] = 0ull; acc1[r] = 0ull; }

    const ulonglong2* Wv = (const ulonglong2*)Wp;  // [KP][64] of ulonglong2
    const float* srow = &src[eg * 8 * sstride];
#pragma unroll 4
    for (int kp = 0; kp < KP; kp++) {
        ulonglong2 w = Wv[kp * 64 + cg];           // cols 2cg, 2cg+1
#pragma unroll
        for (int r = 0; r < 8; r++) {
            unsigned long long xv = *(const unsigned long long*)&srow[r * sstride + kp * 2];
            FMA2(acc0[r], xv, w.x, acc0[r]);
            FMA2(acc1[r], xv, w.y, acc1[r]);
        }
    }
    float2 bb = *(const float2*)&bias[cg * 2];
#pragma unroll
    for (int r = 0; r < 8; r++) {
        float2 o;
        o.x = silu_f(lo_f(acc0[r]) + hi_f(acc0[r]) + bb.x);
        o.y = silu_f(lo_f(acc1[r]) + hi_f(acc1[r]) + bb.y);
        *(float2*)&dst[(eg * 8 + r) * MS + cg * 2] = o;
    }
}

__global__ __launch_bounds__(NTHR, 2)
void edge_kernel(const float* __restrict__ h,
                 const float* __restrict__ coords,
                 const float* __restrict__ ca,
                 const float* __restrict__ cw,
                 const float* __restrict__ edge_weights,
                 const int* __restrict__ el,
                 const float* __restrict__ rl_w,
                 const float* __restrict__ rl_b,
                 const float* __restrict__ m_b1,
                 const float* __restrict__ m_b2,
                 const float* __restrict__ c_b1,
                 const float* __restrict__ w_r) {
    extern __shared__ char smem_raw[];
    EdgeSmem& sm = *reinterpret_cast<EdgeSmem*>(smem_raw);

    const int tid = threadIdx.x;
    const int wid = tid >> 5;
    const int lane = tid & 31;
    const long tileBase = (long)blockIdx.x * TILE_E;

    float gmax = sqrtf(__uint_as_float(g_maxbits));
    float inv_g = 1.f / (gmax + 0.001f);

    float* WS  = &sm.wscr[wid][0];
    float* At  = WS;
    float* Bs  = WS + 64;
    float* Mm  = WS + 128;
    float* Tt  = WS + 192;
    float* cwt = WS + 256;
    float* cws = WS + 264;
    float* ctb = WS + 272;
    float* csb = WS + 296;

    // ---- Phase A: per-edge preprocessing (each of 8 warps handles 4 edges) ----
    for (int i = 0; i < 4; i++) {
        int e = wid * 4 + i;
        long ge = tileBase + e;
        bool valid = (ge < (long)EE);
        int src = 0, tgt = 0, rel = 0;
        if (valid) {
            src = el[ge * 3 + 0];
            tgt = el[ge * 3 + 1];
            rel = el[ge * 3 + 2];
        }
        if (lane == 0) {
            sm.s_tgt[e] = valid ? tgt : -1;
            sm.s_ew[e]  = valid ? edge_weights[ge] : 0.f;
            sm.s_wr[e]  = valid ? w_r[rel] : 0.f;
            int cs = valid ? g_csum[tgt] : 1;
            int ts = cs - 1;
            ts = ts < 0 ? 0 : (ts > 7 ? 7 : ts);
            sm.s_ts[e] = ts;
        }
        if (!valid) {
            for (int k = lane; k < 264; k += 32) sm.xs[e * XS + k] = 0.f;
            for (int k = lane; k < 24;  k += 32) sm.cdiff[e * 24 + k] = 0.f;
            __syncwarp();
            continue;
        }
        // stage per-edge operands
        At[lane]      = ca[(long)tgt * 64 + lane];
        At[lane + 32] = ca[(long)tgt * 64 + lane + 32];
        Bs[lane]      = ca[(long)src * 64 + lane];
        Bs[lane + 32] = ca[(long)src * 64 + lane + 32];
        if (lane < 8) { cwt[lane] = cw[(long)tgt * 8 + lane]; cws[lane] = cw[(long)src * 8 + lane]; }
        if (lane < 24) { ctb[lane] = coords[(long)tgt * 24 + lane]; csb[lane] = coords[(long)src * 24 + lane]; }
        __syncwarp();

        // M[c][d] = (||ct_c - cs_d|| / (gmax+eps)) * cwt[c]*cws[d]
#pragma unroll
        for (int half = 0; half < 2; half++) {
            int idx = lane + half * 32;
            int c = idx >> 3, d = idx & 7;
            float dx = ctb[c * 3 + 0] - csb[d * 3 + 0];
            float dy = ctb[c * 3 + 1] - csb[d * 3 + 1];
            float dz = ctb[c * 3 + 2] - csb[d * 3 + 2];
            float ns = dx * dx + dy * dy + dz * dz;
            float nrm = (ns > 0.f) ? ns * rsqrtf(ns) : 0.f;
            Mm[idx] = nrm * inv_g * cwt[c] * cws[d];
        }
        __syncwarp();

        // T[a][d] = sum_c At[c][a] * M[c][d]
#pragma unroll
        for (int half = 0; half < 2; half++) {
            int idx = lane + half * 32;
            int a = idx >> 3, d = idx & 7;
            float t = 0.f;
#pragma unroll
            for (int c = 0; c < 8; c++) t = fmaf(At[c * 8 + a], Mm[c * 8 + d], t);
            Tt[idx] = t;
        }
        __syncwarp();

        // R[a][b] = sum_d T[a][d] * Bs[d][b]
        float r0 = 0.f, r1 = 0.f;
        {
            int a = lane >> 3, b = lane & 7;
#pragma unroll
            for (int d = 0; d < 8; d++) r0 = fmaf(Tt[a * 8 + d], Bs[d * 8 + b], r0);
            int idx = lane + 32;
            a = idx >> 3; b = idx & 7;
#pragma unroll
            for (int d = 0; d < 8; d++) r1 = fmaf(Tt[a * 8 + d], Bs[d * 8 + b], r1);
        }
        float ss = r0 * r0 + r1 * r1;
#pragma unroll
        for (int o = 16; o > 0; o >>= 1) ss += __shfl_xor_sync(0xffffffffu, ss, o);
        float invn = 1.f / (sqrtf(ss) + 0.001f);
        Mm[lane] = r0;           // reuse M as flattened R
        Mm[lane + 32] = r1;
        __syncwarp();

        // radial_out[j] = (R . rl_w[:,j]) * invn + rl_b[j]  -> xs[e][256+j]
        if (lane < 8) {
            float acc = 0.f;
#pragma unroll
            for (int k = 0; k < 64; k++) acc = fmaf(Mm[k], rl_w[k * 8 + lane], acc);
            sm.xs[e * XS + 256 + lane] = acc * invn + rl_b[lane];
        }
        // gather h[tgt], h[src] -> xs[e][0..255]
        ((float4*)&sm.xs[e * XS])[lane]      = ((const float4*)(h + (long)tgt * 128))[lane];
        ((float4*)&sm.xs[e * XS])[lane + 32] = ((const float4*)(h + (long)src * 128))[lane];
        // coord_diff = coords[tgt] - pooled_col[src]
        if (lane < 24) {
            int k = lane % 3;
            sm.cdiff[e * 24 + lane] = ctb[lane] - g_pcol[(long)src * 3 + k];
        }
        __syncwarp();
    }
    __syncthreads();

    // ---- GEMM chain (packed-K FFMA2, 8 rows x 2 cols per thread) ----
    tile_gemm<132>(sm.xs,  XS, g_W1p,  m_b1, sm.ms1, tid);  // m1 = silu(x@W1+b1)
    __syncthreads();
    tile_gemm<64>(sm.ms1, MS, g_W2p,  m_b2, sm.ms2, tid);   // m  = silu(m1@W2+b2)
    __syncthreads();
    tile_gemm<64>(sm.ms2, MS, g_CW1p, c_b1, sm.ms1, tid);   // cf = silu(m@Cw1+Cb1)
    __syncthreads();

    // edge_feat = cf @ c_w2  (32 edges x 8), packed-K: one output per thread
    {
        int e = tid >> 3;
        int j = tid & 7;
        unsigned long long acc = 0ull;
#pragma unroll 8
        for (int kp = 0; kp < 64; kp++) {
            unsigned long long cf = *(const unsigned long long*)&sm.ms1[e * MS + kp * 2];
            FMA2(acc, cf, g_CW2p[kp * 8 + j], acc);
        }
        sm.ef[e * 8 + j] = lo_f(acc) + hi_f(acc);
    }
    __syncthreads();

    // ---- aggregation atomics ----
    // node_agg[tgt] += m * ew
    for (int idx = tid; idx < TILE_E * 128; idx += NTHR) {
        int e = idx >> 7, j = idx & 127;
        int t = sm.s_tgt[e];
        if (t >= 0)
            atomicAdd(&g_node_agg[(long)t * 128 + j], sm.ms2[e * MS + j] * sm.s_ew[e]);
    }
    // coord_sum[tgt] += w_r * coord_diff * pooled_edge
    for (int idx = tid; idx < TILE_E * 8; idx += NTHR) {
        int e = idx >> 3, a = idx & 7;
        int t = sm.s_tgt[e];
        if (t < 0) continue;
        int ts = sm.s_ts[e];
        int w = 8 - ts;
        int hi = a + w; if (hi > 8) hi = 8;
        float s = 0.f;
        for (int b = a; b < hi; b++) s += sm.ef[e * 8 + b];
        float pe = (s / (float)w) * sm.s_wr[e];
#pragma unroll
        for (int k = 0; k < 3; k++)
            atomicAdd(&g_coord_sum[(long)t * 24 + a * 3 + k], sm.cdiff[e * 24 + a * 3 + k] * pe);
    }
    // cnt[tgt] += 1
    if (tid < TILE_E) {
        int t = sm.s_tgt[tid];
        if (t >= 0) atomicAdd(&g_cnt[t], 1.f);
    }
}

// ---------------- node epilogue: out GEMM + BN + silu + residuals ----------------
__global__ __launch_bounds__(512, 1)
void node_out_kernel(const float* __restrict__ h,
                     const float* __restrict__ coords,
                     const float* __restrict__ het_b,
                     const float* __restrict__ gamma,
                     const float* __restrict__ beta,
                     float* __restrict__ out) {
    __shared__ float ag[64 * MS];
    const int tid = threadIdx.x;
    const int base = blockIdx.x * 64;
    const float INVS = 0.9999950000374996f;  // 1/sqrt(1+1e-5)

    for (int idx = tid; idx < 64 * 128; idx += 512) {
        int n = idx >> 7, k = idx & 127;
        int gn = base + n;
        ag[n * MS + k] = (gn < NN) ? g_node_agg[(long)gn * 128 + k] : 0.f;
    }
    __syncthreads();

    const int cg = tid & 63;
    const int ng = tid >> 6;
    unsigned long long acc0[8], acc1[8];
#pragma unroll
    for (int r = 0; r < 8; r++) { acc0[r] = 0ull; acc1[r] = 0ull; }
    const ulonglong2* Wv = (const ulonglong2*)g_HWp;
#pragma unroll 4
    for (int kp = 0; kp < 64; kp++) {
        ulonglong2 w = Wv[kp * 64 + cg];
#pragma unroll
        for (int r = 0; r < 8; r++) {
            unsigned long long xv = *(const unsigned long long*)&ag[(ng * 8 + r) * MS + kp * 2];
            FMA2(acc0[r], xv, w.x, acc0[r]);
            FMA2(acc1[r], xv, w.y, acc1[r]);
        }
    }
    int j0 = cg * 2;
    float2 hb = *(const float2*)&het_b[j0];
    float2 gm = *(const float2*)&gamma[j0];
    float2 bt = *(const float2*)&beta[j0];
#pragma unroll
    for (int r = 0; r < 8; r++) {
        int gn = base + ng * 8 + r;
        if (gn < NN) {
            float2 o;
            o.x = silu_f((lo_f(acc0[r]) + hi_f(acc0[r]) + hb.x) * INVS * gm.x + bt.x);
            o.y = silu_f((lo_f(acc1[r]) + hi_f(acc1[r]) + hb.y) * INVS * gm.y + bt.y);
            float2 hv = *(const float2*)&h[(long)gn * 128 + j0];
            o.x += hv.x; o.y += hv.y;
            *(float2*)&out[(long)gn * 128 + j0] = o;
        }
    }

    // coord_output = coords + coord_sum / max(cnt,1)
    for (int idx = tid; idx < 64 * 24; idx += 512) {
        int n = idx / 24, k = idx % 24;
        int gn = base + n;
        if (gn < NN) {
            float c = fmaxf(g_cnt[gn], 1.f);
            out[(long)NN * 128 + (long)gn * 24 + k] =
                coords[(long)gn * 24 + k] + g_coord_sum[(long)gn * 24 + k] / c;
        }
    }
}

// ---------------- launch ----------------
extern "C" void kernel_launch(void* const* d_in, const int* in_sizes, int n_in,
                              void* d_out, int out_size) {
    (void)in_sizes; (void)n_in; (void)out_size;
    const float* h      = (const float*)d_in[0];
    const float* coords = (const float*)d_in[1];
    const float* ca     = (const float*)d_in[2];
    const float* cw     = (const float*)d_in[3];
    const float* ew     = (const float*)d_in[4];
    const int*   el     = (const int*)d_in[5];
    const float* rl_w   = (const float*)d_in[6];
    const float* rl_b   = (const float*)d_in[7];
    const float* m_w1   = (const float*)d_in[8];
    const float* m_b1   = (const float*)d_in[9];
    const float* m_w2   = (const float*)d_in[10];
    const float* m_b2   = (const float*)d_in[11];
    const float* c_w1   = (const float*)d_in[12];
    const float* c_b1   = (const float*)d_in[13];
    const float* c_w2   = (const float*)d_in[14];
    const float* het_w  = (const float*)d_in[15];
    const float* het_b  = (const float*)d_in[16];
    const float* gamma  = (const float*)d_in[17];
    const float* beta   = (const float*)d_in[18];
    const float* w_r    = (const float*)d_in[19];
    float* out = (float*)d_out;

    cudaFuncSetAttribute(edge_kernel, cudaFuncAttributeMaxDynamicSharedMemorySize,
                         (int)sizeof(EdgeSmem));

    zero_kernel<<<2048, 256>>>();
    pack_kernel<<<132, 256>>>(m_w1, m_w2, c_w1, c_w2, het_w);
    node_pre_kernel<<<(NN + 255) / 256, 256>>>(coords, cw);
    max_kernel<<<(EE + 255) / 256, 256>>>(coords, el);
    edge_kernel<<<(EE + TILE_E - 1) / TILE_E, NTHR, sizeof(EdgeSmem)>>>(
        h, coords, ca, cw, ew, el, rl_w, rl_b,
        m_b1, m_b2, c_b1, w_r);
    node_out_kernel<<<(NN + 63) / 64, 512>>>(h, coords, het_b, gamma, beta, out);
}

// round 5
// speedup vs baseline: 1.7787x; 1.2330x over previous
#include <cuda_runtime.h>
#include <math.h>

#define NN 50000
#define EE 400000
#define DD 128
#define CC 8

#define TILE_E 32
#define NTHR 256
#define MS 132   // intermediate row stride (128 used, 8B-aligned rows)

// ---------------- device scratch (no allocations allowed) ----------------
__device__ float g_node_agg[NN * DD];        // 25.6 MB
__device__ float g_coord_sum[NN * CC * 3];   // 4.8 MB
__device__ float g_cnt[NN];
__device__ float g_pcol[NN * 3];
__device__ int   g_csum[NN];
__device__ unsigned int g_maxbits;
__device__ float g_Ah[NN * DD];              // h @ W1[:128]
__device__ float g_Bh[NN * DD];              // h @ W1[128:256]

// K-pair-interleaved packed weights: element [kp*COLS + j] = pack(w[2kp][j], w[2kp+1][j])
__device__ unsigned long long g_W1p[128 * 128];   // m_w1 rows 0..255 (kp 0..63 = W1a, 64..127 = W1b)
__device__ unsigned long long g_W2p[64 * 128];    // m_w2: 128x128
__device__ unsigned long long g_CW1p[64 * 128];   // c_w1: 128x128
__device__ unsigned long long g_HWp[64 * 128];    // het_w: 128x128
__device__ unsigned long long g_CW2p[64 * 8];     // c_w2: 128x8

__device__ __forceinline__ float silu_f(float x) {
    return x * (1.0f / (1.0f + __expf(-x)));
}

__device__ __forceinline__ unsigned long long packf2(float lo, float hi) {
    return ((unsigned long long)__float_as_uint(hi) << 32) | (unsigned long long)__float_as_uint(lo);
}
__device__ __forceinline__ float lo_f(unsigned long long p) { return __uint_as_float((unsigned)(p & 0xffffffffull)); }
__device__ __forceinline__ float hi_f(unsigned long long p) { return __uint_as_float((unsigned)(p >> 32)); }

#define FMA2(d, a, b, c) asm("fma.rn.f32x2 %0, %1, %2, %3;" : "=l"(d) : "l"(a), "l"(b), "l"(c))

// ---------------- zero scratch ----------------
__global__ void zero_kernel() {
    long t0 = (long)blockIdx.x * blockDim.x + threadIdx.x;
    long stride = (long)gridDim.x * blockDim.x;
    for (long i = t0; i < (long)NN * DD; i += stride) g_node_agg[i] = 0.f;
    for (long i = t0; i < (long)NN * 24; i += stride) g_coord_sum[i] = 0.f;
    for (long i = t0; i < NN; i += stride) g_cnt[i] = 0.f;
    if (t0 == 0) g_maxbits = 0u;
}

// ---------------- weight pre-packing (K-pair interleave) ----------------
__global__ void pack_kernel(const float* __restrict__ m_w1,
                            const float* __restrict__ m_w2,
                            const float* __restrict__ c_w1,
                            const float* __restrict__ c_w2,
                            const float* __restrict__ het_w) {
    int t0 = blockIdx.x * blockDim.x + threadIdx.x;
    int stride = gridDim.x * blockDim.x;
    for (int i = t0; i < 128 * 128; i += stride) {
        int kp = i >> 7, j = i & 127;
        g_W1p[i] = packf2(m_w1[(2 * kp) * 128 + j], m_w1[(2 * kp + 1) * 128 + j]);
    }
    for (int i = t0; i < 64 * 128; i += stride) {
        int kp = i >> 7, j = i & 127;
        g_W2p[i]  = packf2(m_w2[(2 * kp) * 128 + j],  m_w2[(2 * kp + 1) * 128 + j]);
        g_CW1p[i] = packf2(c_w1[(2 * kp) * 128 + j],  c_w1[(2 * kp + 1) * 128 + j]);
        g_HWp[i]  = packf2(het_w[(2 * kp) * 128 + j], het_w[(2 * kp + 1) * 128 + j]);
    }
    for (int i = t0; i < 64 * 8; i += stride) {
        int kp = i >> 3, j = i & 7;
        g_CW2p[i] = packf2(c_w2[(2 * kp) * 8 + j], c_w2[(2 * kp + 1) * 8 + j]);
    }
}

// ---------------- per-node precompute: csum, pooled_col ----------------
__global__ void node_pre_kernel(const float* __restrict__ coords,
                                const float* __restrict__ cw) {
    int n = blockIdx.x * blockDim.x + threadIdx.x;
    if (n >= NN) return;
    float px = 0.f, py = 0.f, pz = 0.f;
    int cs = 0;
#pragma unroll
    for (int c = 0; c < 8; c++) {
        float w = cw[n * 8 + c];
        if (w != 0.f) {
            cs++;
            px += coords[n * 24 + c * 3 + 0];
            py += coords[n * 24 + c * 3 + 1];
            pz += coords[n * 24 + c * 3 + 2];
        }
    }
    float inv = 1.f / ((float)cs + 0.001f);
    g_pcol[n * 3 + 0] = px * inv;
    g_pcol[n * 3 + 1] = py * inv;
    g_pcol[n * 3 + 2] = pz * inv;
    g_csum[n] = cs;
}

// ---------------- global max of squared channel distances ----------------
__global__ void max_kernel(const float* __restrict__ coords,
                           const int* __restrict__ el) {
    int e = blockIdx.x * blockDim.x + threadIdx.x;
    float m = 0.f;
    if (e < EE) {
        int src = el[e * 3 + 0];
        int tgt = el[e * 3 + 1];
        float ct[24], cs[24];
#pragma unroll
        for (int i = 0; i < 24; i++) {
            ct[i] = coords[(long)tgt * 24 + i];
            cs[i] = coords[(long)src * 24 + i];
        }
#pragma unroll
        for (int c = 0; c < 8; c++) {
#pragma unroll
            for (int d = 0; d < 8; d++) {
                float dx = ct[c * 3 + 0] - cs[d * 3 + 0];
                float dy = ct[c * 3 + 1] - cs[d * 3 + 1];
                float dz = ct[c * 3 + 2] - cs[d * 3 + 2];
                float ns = dx * dx + dy * dy + dz * dz;
                m = fmaxf(m, ns);
            }
        }
    }
#pragma unroll
    for (int o = 16; o > 0; o >>= 1)
        m = fmaxf(m, __shfl_xor_sync(0xffffffffu, m, o));
    if ((threadIdx.x & 31) == 0)
        atomicMax(&g_maxbits, __float_as_uint(m));  // valid for non-negative floats
}

// ---------------- per-node GEMM: Ah = h@W1a, Bh = h@W1b ----------------
__global__ __launch_bounds__(512, 1)
void node_gemm_kernel(const float* __restrict__ h) {
    __shared__ float hs[64 * MS];
    const int tid = threadIdx.x;
    const int base = blockIdx.x * 64;

    for (int idx = tid; idx < 64 * 128; idx += 512) {
        int n = idx >> 7, k = idx & 127;
        int gn = base + n;
        hs[n * MS + k] = (gn < NN) ? h[(long)gn * 128 + k] : 0.f;
    }
    __syncthreads();

    const int cg = tid & 63;
    const int ng = tid >> 6;
#pragma unroll
    for (int half = 0; half < 2; half++) {
        float* dst = half ? g_Bh : g_Ah;
        const ulonglong2* Wv = (const ulonglong2*)(g_W1p + half * 64 * 128);
        unsigned long long acc0[8], acc1[8];
#pragma unroll
        for (int r = 0; r < 8; r++) { acc0[r] = 0ull; acc1[r] = 0ull; }
#pragma unroll 4
        for (int kp = 0; kp < 64; kp++) {
            ulonglong2 w = Wv[kp * 64 + cg];
#pragma unroll
            for (int r = 0; r < 8; r++) {
                unsigned long long xv = *(const unsigned long long*)&hs[(ng * 8 + r) * MS + kp * 2];
                FMA2(acc0[r], xv, w.x, acc0[r]);
                FMA2(acc1[r], xv, w.y, acc1[r]);
            }
        }
#pragma unroll
        for (int r = 0; r < 8; r++) {
            int gn = base + ng * 8 + r;
            if (gn < NN) {
                float2 o;
                o.x = lo_f(acc0[r]) + hi_f(acc0[r]);
                o.y = lo_f(acc1[r]) + hi_f(acc1[r]);
                *(float2*)&dst[(long)gn * 128 + cg * 2] = o;
            }
        }
    }
}

// ---------------- fused edge kernel ----------------
struct EdgeSmem {
    float ms1[TILE_E * MS];    // m1 / cf reuse
    float ms2[TILE_E * MS];    // m (post-GEMM2)
    float wscr[8][320];        // per-warp scratch: At(0) Bs(64) M(128) T(192) cwt(256) cws(264) ct(272) cs(296)
    float w1c[8 * 128];        // m_w1 rows 256..263 (radial part)
    float b1s[128];
    float cdiff[TILE_E * 24];
    float rad[TILE_E * 8];
    float ef[TILE_E * 8];
    int   s_tgt[TILE_E];
    int   s_src[TILE_E];
    float s_ew[TILE_E];
    float s_wr[TILE_E];
    int   s_ts[TILE_E];
};

// 32 (edges) x 128 (cols) GEMM with packed-K FFMA2.
// 256 threads: eg = tid>>6 (4 groups of 8 edges), cg = tid&63 (64 col-pairs).
template <int KP>
__device__ __forceinline__ void tile_gemm(const float* __restrict__ src, int sstride,
                                          const unsigned long long* __restrict__ Wp,
                                          const float* __restrict__ bias,
                                          float* __restrict__ dst, int tid) {
    const int cg = tid & 63;
    const int eg = tid >> 6;
    unsigned long long acc0[8], acc1[8];
#pragma unroll
    for (int r = 0; r < 8; r++) { acc0[r] = 0ull; acc1[r] = 0ull; }

    const ulonglong2* Wv = (const ulonglong2*)Wp;  // [KP][64] of ulonglong2
    const float* srow = &src[eg * 8 * sstride];
#pragma unroll 4
    for (int kp = 0; kp < KP; kp++) {
        ulonglong2 w = Wv[kp * 64 + cg];           // cols 2cg, 2cg+1
#pragma unroll
        for (int r = 0; r < 8; r++) {
            unsigned long long xv = *(const unsigned long long*)&srow[r * sstride + kp * 2];
            FMA2(acc0[r], xv, w.x, acc0[r]);
            FMA2(acc1[r], xv, w.y, acc1[r]);
        }
    }
    float2 bb = *(const float2*)&bias[cg * 2];
#pragma unroll
    for (int r = 0; r < 8; r++) {
        float2 o;
        o.x = silu_f(lo_f(acc0[r]) + hi_f(acc0[r]) + bb.x);
        o.y = silu_f(lo_f(acc1[r]) + hi_f(acc1[r]) + bb.y);
        *(float2*)&dst[(eg * 8 + r) * MS + cg * 2] = o;
    }
}

__global__ __launch_bounds__(NTHR, 3)
void edge_kernel(const float* __restrict__ coords,
                 const float* __restrict__ ca,
                 const float* __restrict__ cw,
                 const float* __restrict__ edge_weights,
                 const int* __restrict__ el,
                 const float* __restrict__ rl_w,
                 const float* __restrict__ rl_b,
                 const float* __restrict__ m_w1,
                 const float* __restrict__ m_b1,
                 const float* __restrict__ m_b2,
                 const float* __restrict__ c_b1,
                 const float* __restrict__ w_r) {
    extern __shared__ char smem_raw[];
    EdgeSmem& sm = *reinterpret_cast<EdgeSmem*>(smem_raw);

    const int tid = threadIdx.x;
    const int wid = tid >> 5;
    const int lane = tid & 31;
    const long tileBase = (long)blockIdx.x * TILE_E;

    float gmax = sqrtf(__uint_as_float(g_maxbits));
    float inv_g = 1.f / (gmax + 0.001f);

    // stage W1c (radial rows) + b1
    for (int i = tid; i < 8 * 128; i += NTHR) sm.w1c[i] = m_w1[256 * 128 + i];
    for (int i = tid; i < 128; i += NTHR) sm.b1s[i] = m_b1[i];

    float* WS  = &sm.wscr[wid][0];
    float* At  = WS;
    float* Bs  = WS + 64;
    float* Mm  = WS + 128;
    float* Tt  = WS + 192;
    float* cwt = WS + 256;
    float* cws = WS + 264;
    float* ctb = WS + 272;
    float* csb = WS + 296;

    // ---- Phase A: per-edge preprocessing (each of 8 warps handles 4 edges) ----
    for (int i = 0; i < 4; i++) {
        int e = wid * 4 + i;
        long ge = tileBase + e;
        bool valid = (ge < (long)EE);
        int src = 0, tgt = 0, rel = 0;
        if (valid) {
            src = el[ge * 3 + 0];
            tgt = el[ge * 3 + 1];
            rel = el[ge * 3 + 2];
        }
        if (lane == 0) {
            sm.s_tgt[e] = valid ? tgt : -1;
            sm.s_src[e] = src;
            sm.s_ew[e]  = valid ? edge_weights[ge] : 0.f;
            sm.s_wr[e]  = valid ? w_r[rel] : 0.f;
            int cs = valid ? g_csum[tgt] : 1;
            int ts = cs - 1;
            ts = ts < 0 ? 0 : (ts > 7 ? 7 : ts);
            sm.s_ts[e] = ts;
        }
        if (!valid) {
            if (lane < 8)  sm.rad[e * 8 + lane] = 0.f;
            if (lane < 24) sm.cdiff[e * 24 + lane] = 0.f;
            __syncwarp();
            continue;
        }
        // stage per-edge operands
        At[lane]      = ca[(long)tgt * 64 + lane];
        At[lane + 32] = ca[(long)tgt * 64 + lane + 32];
        Bs[lane]      = ca[(long)src * 64 + lane];
        Bs[lane + 32] = ca[(long)src * 64 + lane + 32];
        if (lane < 8) { cwt[lane] = cw[(long)tgt * 8 + lane]; cws[lane] = cw[(long)src * 8 + lane]; }
        if (lane < 24) { ctb[lane] = coords[(long)tgt * 24 + lane]; csb[lane] = coords[(long)src * 24 + lane]; }
        __syncwarp();

        // M[c][d] = (||ct_c - cs_d|| / (gmax+eps)) * cwt[c]*cws[d]
#pragma unroll
        for (int half = 0; half < 2; half++) {
            int idx = lane + half * 32;
            int c = idx >> 3, d = idx & 7;
            float dx = ctb[c * 3 + 0] - csb[d * 3 + 0];
            float dy = ctb[c * 3 + 1] - csb[d * 3 + 1];
            float dz = ctb[c * 3 + 2] - csb[d * 3 + 2];
            float ns = dx * dx + dy * dy + dz * dz;
            float nrm = (ns > 0.f) ? ns * rsqrtf(ns) : 0.f;
            Mm[idx] = nrm * inv_g * cwt[c] * cws[d];
        }
        __syncwarp();

        // T[a][d] = sum_c At[c][a] * M[c][d]
#pragma unroll
        for (int half = 0; half < 2; half++) {
            int idx = lane + half * 32;
            int a = idx >> 3, d = idx & 7;
            float t = 0.f;
#pragma unroll
            for (int c = 0; c < 8; c++) t = fmaf(At[c * 8 + a], Mm[c * 8 + d], t);
            Tt[idx] = t;
        }
        __syncwarp();

        // R[a][b] = sum_d T[a][d] * Bs[d][b]
        float r0 = 0.f, r1 = 0.f;
        {
            int a = lane >> 3, b = lane & 7;
#pragma unroll
            for (int d = 0; d < 8; d++) r0 = fmaf(Tt[a * 8 + d], Bs[d * 8 + b], r0);
            int idx = lane + 32;
            a = idx >> 3; b = idx & 7;
#pragma unroll
            for (int d = 0; d < 8; d++) r1 = fmaf(Tt[a * 8 + d], Bs[d * 8 + b], r1);
        }
        float ss = r0 * r0 + r1 * r1;
#pragma unroll
        for (int o = 16; o > 0; o >>= 1) ss += __shfl_xor_sync(0xffffffffu, ss, o);
        float invn = 1.f / (sqrtf(ss) + 0.001f);
        Mm[lane] = r0;           // reuse M as flattened R
        Mm[lane + 32] = r1;
        __syncwarp();

        // radial_out[j] = (R . rl_w[:,j]) * invn + rl_b[j]  -> rad[e][j]
        if (lane < 8) {
            float acc = 0.f;
#pragma unroll
            for (int k = 0; k < 64; k++) acc = fmaf(Mm[k], rl_w[k * 8 + lane], acc);
            sm.rad[e * 8 + lane] = acc * invn + rl_b[lane];
        }
        // coord_diff = coords[tgt] - pooled_col[src]
        if (lane < 24) {
            int k = lane % 3;
            sm.cdiff[e * 24 + lane] = ctb[lane] - g_pcol[(long)src * 3 + k];
        }
        __syncwarp();
    }
    __syncthreads();

    // ---- m1 = silu(Ah[tgt] + Bh[src] + rad @ W1c + b1) ----
    {
        const int e = tid >> 3;          // 32 edges
        const int q = tid & 7;           // 8 col-quarters of 16
        const int j0 = q * 16;
        int t = sm.s_tgt[e];
        int s = sm.s_src[e];
        float r[8];
#pragma unroll
        for (int k = 0; k < 8; k++) r[k] = sm.rad[e * 8 + k];
        if (t >= 0) {
#pragma unroll
            for (int v = 0; v < 4; v++) {
                int j = j0 + v * 4;
                float4 a  = *(const float4*)&g_Ah[(long)t * 128 + j];
                float4 b  = *(const float4*)&g_Bh[(long)s * 128 + j];
                float4 bb = *(const float4*)&sm.b1s[j];
                float4 acc;
                acc.x = a.x + b.x + bb.x;
                acc.y = a.y + b.y + bb.y;
                acc.z = a.z + b.z + bb.z;
                acc.w = a.w + b.w + bb.w;
#pragma unroll
                for (int k = 0; k < 8; k++) {
                    float4 w = *(const float4*)&sm.w1c[k * 128 + j];
                    acc.x = fmaf(r[k], w.x, acc.x);
                    acc.y = fmaf(r[k], w.y, acc.y);
                    acc.z = fmaf(r[k], w.z, acc.z);
                    acc.w = fmaf(r[k], w.w, acc.w);
                }
                float4 o;
                o.x = silu_f(acc.x); o.y = silu_f(acc.y);
                o.z = silu_f(acc.z); o.w = silu_f(acc.w);
                *(float4*)&sm.ms1[e * MS + j] = o;
            }
        } else {
#pragma unroll
            for (int v = 0; v < 4; v++)
                *(float4*)&sm.ms1[e * MS + j0 + v * 4] = make_float4(0.f, 0.f, 0.f, 0.f);
        }
    }
    __syncthreads();

    // ---- GEMM chain (packed-K FFMA2, 8 rows x 2 cols per thread) ----
    tile_gemm<64>(sm.ms1, MS, g_W2p,  m_b2, sm.ms2, tid);   // m  = silu(m1@W2+b2)
    __syncthreads();
    tile_gemm<64>(sm.ms2, MS, g_CW1p, c_b1, sm.ms1, tid);   // cf = silu(m@Cw1+Cb1)
    __syncthreads();

    // edge_feat = cf @ c_w2  (32 edges x 8), packed-K: one output per thread
    {
        int e = tid >> 3;
        int j = tid & 7;
        unsigned long long acc = 0ull;
#pragma unroll 8
        for (int kp = 0; kp < 64; kp++) {
            unsigned long long cf = *(const unsigned long long*)&sm.ms1[e * MS + kp * 2];
            FMA2(acc, cf, g_CW2p[kp * 8 + j], acc);
        }
        sm.ef[e * 8 + j] = lo_f(acc) + hi_f(acc);
    }
    __syncthreads();

    // ---- aggregation atomics ----
    // node_agg[tgt] += m * ew
    for (int idx = tid; idx < TILE_E * 128; idx += NTHR) {
        int e = idx >> 7, j = idx & 127;
        int t = sm.s_tgt[e];
        if (t >= 0)
            atomicAdd(&g_node_agg[(long)t * 128 + j], sm.ms2[e * MS + j] * sm.s_ew[e]);
    }
    // coord_sum[tgt] += w_r * coord_diff * pooled_edge
    for (int idx = tid; idx < TILE_E * 8; idx += NTHR) {
        int e = idx >> 3, a = idx & 7;
        int t = sm.s_tgt[e];
        if (t < 0) continue;
        int ts = sm.s_ts[e];
        int w = 8 - ts;
        int hi = a + w; if (hi > 8) hi = 8;
        float s = 0.f;
        for (int b = a; b < hi; b++) s += sm.ef[e * 8 + b];
        float pe = (s / (float)w) * sm.s_wr[e];
#pragma unroll
        for (int k = 0; k < 3; k++)
            atomicAdd(&g_coord_sum[(long)t * 24 + a * 3 + k], sm.cdiff[e * 24 + a * 3 + k] * pe);
    }
    // cnt[tgt] += 1
    if (tid < TILE_E) {
        int t = sm.s_tgt[tid];
        if (t >= 0) atomicAdd(&g_cnt[t], 1.f);
    }
}

// ---------------- node epilogue: out GEMM + BN + silu + residuals ----------------
__global__ __launch_bounds__(512, 1)
void node_out_kernel(const float* __restrict__ h,
                     const float* __restrict__ coords,
                     const float* __restrict__ het_b,
                     const float* __restrict__ gamma,
                     const float* __restrict__ beta,
                     float* __restrict__ out) {
    __shared__ float ag[64 * MS];
    const int tid = threadIdx.x;
    const int base = blockIdx.x * 64;
    const float INVS = 0.9999950000374996f;  // 1/sqrt(1+1e-5)

    for (int idx = tid; idx < 64 * 128; idx += 512) {
        int n = idx >> 7, k = idx & 127;
        int gn = base + n;
        ag[n * MS + k] = (gn < NN) ? g_node_agg[(long)gn * 128 + k] : 0.f;
    }
    __syncthreads();

    const int cg = tid & 63;
    const int ng = tid >> 6;
    unsigned long long acc0[8], acc1[8];
#pragma unroll
    for (int r = 0; r < 8; r++) { acc0[r] = 0ull; acc1[r] = 0ull; }
    const ulonglong2* Wv = (const ulonglong2*)g_HWp;
#pragma unroll 4
    for (int kp = 0; kp < 64; kp++) {
        ulonglong2 w = Wv[kp * 64 + cg];
#pragma unroll
        for (int r = 0; r < 8; r++) {
            unsigned long long xv = *(const unsigned long long*)&ag[(ng * 8 + r) * MS + kp * 2];
            FMA2(acc0[r], xv, w.x, acc0[r]);
            FMA2(acc1[r], xv, w.y, acc1[r]);
        }
    }
    int j0 = cg * 2;
    float2 hb = *(const float2*)&het_b[j0];
    float2 gm = *(const float2*)&gamma[j0];
    float2 bt = *(const float2*)&beta[j0];
#pragma unroll
    for (int r = 0; r < 8; r++) {
        int gn = base + ng * 8 + r;
        if (gn < NN) {
            float2 o;
            o.x = silu_f((lo_f(acc0[r]) + hi_f(acc0[r]) + hb.x) * INVS * gm.x + bt.x);
            o.y = silu_f((lo_f(acc1[r]) + hi_f(acc1[r]) + hb.y) * INVS * gm.y + bt.y);
            float2 hv = *(const float2*)&h[(long)gn * 128 + j0];
            o.x += hv.x; o.y += hv.y;
            *(float2*)&out[(long)gn * 128 + j0] = o;
        }
    }

    // coord_output = coords + coord_sum / max(cnt,1)
    for (int idx = tid; idx < 64 * 24; idx += 512) {
        int n = idx / 24, k = idx % 24;
        int gn = base + n;
        if (gn < NN) {
            float c = fmaxf(g_cnt[gn], 1.f);
            out[(long)NN * 128 + (long)gn * 24 + k] =
                coords[(long)gn * 24 + k] + g_coord_sum[(long)gn * 24 + k] / c;
        }
    }
}

// ---------------- launch ----------------
extern "C" void kernel_launch(void* const* d_in, const int* in_sizes, int n_in,
                              void* d_out, int out_size) {
    (void)in_sizes; (void)n_in; (void)out_size;
    const float* h      = (const float*)d_in[0];
    const float* coords = (const float*)d_in[1];
    const float* ca     = (const float*)d_in[2];
    const float* cw     = (const float*)d_in[3];
    const float* ew     = (const float*)d_in[4];
    const int*   el     = (const int*)d_in[5];
    const float* rl_w   = (const float*)d_in[6];
    const float* rl_b   = (const float*)d_in[7];
    const float* m_w1   = (const float*)d_in[8];
    const float* m_b1   = (const float*)d_in[9];
    const float* m_w2   = (const float*)d_in[10];
    const float* m_b2   = (const float*)d_in[11];
    const float* c_w1   = (const float*)d_in[12];
    const float* c_b1   = (const float*)d_in[13];
    const float* c_w2   = (const float*)d_in[14];
    const float* het_w  = (const float*)d_in[15];
    const float* het_b  = (const float*)d_in[16];
    const float* gamma  = (const float*)d_in[17];
    const float* beta   = (const float*)d_in[18];
    const float* w_r    = (const float*)d_in[19];
    float* out = (float*)d_out;

    cudaFuncSetAttribute(edge_kernel, cudaFuncAttributeMaxDynamicSharedMemorySize,
                         (int)sizeof(EdgeSmem));

    zero_kernel<<<2048, 256>>>();
    pack_kernel<<<132, 256>>>(m_w1, m_w2, c_w1, c_w2, het_w);
    node_pre_kernel<<<(NN + 255) / 256, 256>>>(coords, cw);
    node_gemm_kernel<<<(NN + 63) / 64, 512>>>(h);
    max_kernel<<<(EE + 255) / 256, 256>>>(coords, el);
    edge_kernel<<<(EE + TILE_E - 1) / TILE_E, NTHR, sizeof(EdgeSmem)>>>(
        coords, ca, cw, ew, el, rl_w, rl_b, m_w1,
        m_b1, m_b2, c_b1, w_r);
    node_out_kernel<<<(NN + 63) / 64, 512>>>(h, coords, het_b, gamma, beta, out);
}

// round 6
// speedup vs baseline: 1.9044x; 1.0706x over previous
#include <cuda_runtime.h>
#include <math.h>

#define NN 50000
#define EE 400000
#define DD 128
#define CC 8

#define TILE_E 32
#define NTHR 256
#define MS 132   // intermediate row stride (128 used, 8B-aligned rows)

// ---------------- device scratch (no allocations allowed) ----------------
__device__ float g_node_agg[NN * DD];        // 25.6 MB
__device__ float g_coord_sum[NN * CC * 3];   // 4.8 MB
__device__ float g_cnt[NN];
__device__ float g_pcol[NN * 3];
__device__ int   g_csum[NN];
__device__ unsigned int g_maxbits;
__device__ float g_Ah[NN * DD];              // h @ W1[:128]
__device__ float g_Bh[NN * DD];              // h @ W1[128:256]

// edge-pre outputs
__device__ float g_rad[EE * 8];              // radial MLP output (12.8 MB)
__device__ float g_cdiff[EE * 24];           // coord_diff (38.4 MB)
__device__ int4  g_meta[EE];                 // {tgt, src, ts, ew_bits}
__device__ float g_wr[EE];

// K-pair-interleaved packed weights: element [kp*COLS + j] = pack(w[2kp][j], w[2kp+1][j])
__device__ unsigned long long g_W1p[128 * 128];   // m_w1 rows 0..255 (kp 0..63 = W1a, 64..127 = W1b)
__device__ unsigned long long g_W2p[64 * 128];    // m_w2: 128x128
__device__ unsigned long long g_CW1p[64 * 128];   // c_w1: 128x128
__device__ unsigned long long g_HWp[64 * 128];    // het_w: 128x128
__device__ unsigned long long g_CW2p[64 * 8];     // c_w2: 128x8

__device__ __forceinline__ float silu_f(float x) {
    return x * (1.0f / (1.0f + __expf(-x)));
}

__device__ __forceinline__ unsigned long long packf2(float lo, float hi) {
    return ((unsigned long long)__float_as_uint(hi) << 32) | (unsigned long long)__float_as_uint(lo);
}
__device__ __forceinline__ float lo_f(unsigned long long p) { return __uint_as_float((unsigned)(p & 0xffffffffull)); }
__device__ __forceinline__ float hi_f(unsigned long long p) { return __uint_as_float((unsigned)(p >> 32)); }

#define FMA2(d, a, b, c) asm("fma.rn.f32x2 %0, %1, %2, %3;" : "=l"(d) : "l"(a), "l"(b), "l"(c))

// ---------------- zero scratch ----------------
__global__ void zero_kernel() {
    long t0 = (long)blockIdx.x * blockDim.x + threadIdx.x;
    long stride = (long)gridDim.x * blockDim.x;
    for (long i = t0; i < (long)NN * DD; i += stride) g_node_agg[i] = 0.f;
    for (long i = t0; i < (long)NN * 24; i += stride) g_coord_sum[i] = 0.f;
    for (long i = t0; i < NN; i += stride) g_cnt[i] = 0.f;
    if (t0 == 0) g_maxbits = 0u;
}

// ---------------- weight pre-packing (K-pair interleave) ----------------
__global__ void pack_kernel(const float* __restrict__ m_w1,
                            const float* __restrict__ m_w2,
                            const float* __restrict__ c_w1,
                            const float* __restrict__ c_w2,
                            const float* __restrict__ het_w) {
    int t0 = blockIdx.x * blockDim.x + threadIdx.x;
    int stride = gridDim.x * blockDim.x;
    for (int i = t0; i < 128 * 128; i += stride) {
        int kp = i >> 7, j = i & 127;
        g_W1p[i] = packf2(m_w1[(2 * kp) * 128 + j], m_w1[(2 * kp + 1) * 128 + j]);
    }
    for (int i = t0; i < 64 * 128; i += stride) {
        int kp = i >> 7, j = i & 127;
        g_W2p[i]  = packf2(m_w2[(2 * kp) * 128 + j],  m_w2[(2 * kp + 1) * 128 + j]);
        g_CW1p[i] = packf2(c_w1[(2 * kp) * 128 + j],  c_w1[(2 * kp + 1) * 128 + j]);
        g_HWp[i]  = packf2(het_w[(2 * kp) * 128 + j], het_w[(2 * kp + 1) * 128 + j]);
    }
    for (int i = t0; i < 64 * 8; i += stride) {
        int kp = i >> 3, j = i & 7;
        g_CW2p[i] = packf2(c_w2[(2 * kp) * 8 + j], c_w2[(2 * kp + 1) * 8 + j]);
    }
}

// ---------------- per-node precompute: csum, pooled_col ----------------
__global__ void node_pre_kernel(const float* __restrict__ coords,
                                const float* __restrict__ cw) {
    int n = blockIdx.x * blockDim.x + threadIdx.x;
    if (n >= NN) return;
    float px = 0.f, py = 0.f, pz = 0.f;
    int cs = 0;
#pragma unroll
    for (int c = 0; c < 8; c++) {
        float w = cw[n * 8 + c];
        if (w != 0.f) {
            cs++;
            px += coords[n * 24 + c * 3 + 0];
            py += coords[n * 24 + c * 3 + 1];
            pz += coords[n * 24 + c * 3 + 2];
        }
    }
    float inv = 1.f / ((float)cs + 0.001f);
    g_pcol[n * 3 + 0] = px * inv;
    g_pcol[n * 3 + 1] = py * inv;
    g_pcol[n * 3 + 2] = pz * inv;
    g_csum[n] = cs;
}

// ---------------- global max of squared channel distances ----------------
__global__ void max_kernel(const float* __restrict__ coords,
                           const int* __restrict__ el) {
    int e = blockIdx.x * blockDim.x + threadIdx.x;
    float m = 0.f;
    if (e < EE) {
        int src = el[e * 3 + 0];
        int tgt = el[e * 3 + 1];
        float ct[24], cs[24];
#pragma unroll
        for (int i = 0; i < 24; i++) {
            ct[i] = coords[(long)tgt * 24 + i];
            cs[i] = coords[(long)src * 24 + i];
        }
#pragma unroll
        for (int c = 0; c < 8; c++) {
#pragma unroll
            for (int d = 0; d < 8; d++) {
                float dx = ct[c * 3 + 0] - cs[d * 3 + 0];
                float dy = ct[c * 3 + 1] - cs[d * 3 + 1];
                float dz = ct[c * 3 + 2] - cs[d * 3 + 2];
                float ns = dx * dx + dy * dy + dz * dz;
                m = fmaxf(m, ns);
            }
        }
    }
#pragma unroll
    for (int o = 16; o > 0; o >>= 1)
        m = fmaxf(m, __shfl_xor_sync(0xffffffffu, m, o));
    if ((threadIdx.x & 31) == 0)
        atomicMax(&g_maxbits, __float_as_uint(m));  // valid for non-negative floats
}

// ---------------- per-node GEMM: Ah = h@W1a, Bh = h@W1b ----------------
__global__ __launch_bounds__(NTHR, 3)
void node_gemm_kernel(const float* __restrict__ h) {
    __shared__ float hs[32 * MS];
    const int tid = threadIdx.x;
    const int base = blockIdx.x * 32;

    for (int idx = tid; idx < 32 * 128; idx += NTHR) {
        int n = idx >> 7, k = idx & 127;
        int gn = base + n;
        hs[n * MS + k] = (gn < NN) ? h[(long)gn * 128 + k] : 0.f;
    }
    __syncthreads();

    const int cg = tid & 63;
    const int ng = tid >> 6;
#pragma unroll
    for (int half = 0; half < 2; half++) {
        float* dst = half ? g_Bh : g_Ah;
        const ulonglong2* Wv = (const ulonglong2*)(g_W1p + half * 64 * 128);
        unsigned long long acc0[8], acc1[8];
#pragma unroll
        for (int r = 0; r < 8; r++) { acc0[r] = 0ull; acc1[r] = 0ull; }
#pragma unroll 4
        for (int kp = 0; kp < 64; kp++) {
            ulonglong2 w = Wv[kp * 64 + cg];
#pragma unroll
            for (int r = 0; r < 8; r++) {
                unsigned long long xv = *(const unsigned long long*)&hs[(ng * 8 + r) * MS + kp * 2];
                FMA2(acc0[r], xv, w.x, acc0[r]);
                FMA2(acc1[r], xv, w.y, acc1[r]);
            }
        }
#pragma unroll
        for (int r = 0; r < 8; r++) {
            int gn = base + ng * 8 + r;
            if (gn < NN) {
                float2 o;
                o.x = lo_f(acc0[r]) + hi_f(acc0[r]);
                o.y = lo_f(acc1[r]) + hi_f(acc1[r]);
                *(float2*)&dst[(long)gn * 128 + cg * 2] = o;
            }
        }
    }
}

// ---------------- edge preprocessing: one edge per warp ----------------
__global__ __launch_bounds__(256)
void edge_pre_kernel(const float* __restrict__ coords,
                     const float* __restrict__ ca,
                     const float* __restrict__ cw,
                     const float* __restrict__ edge_weights,
                     const int* __restrict__ el,
                     const float* __restrict__ rl_w,
                     const float* __restrict__ rl_b,
                     const float* __restrict__ w_r) {
    __shared__ float wscr[8][320];
    const int wid = threadIdx.x >> 5;
    const int lane = threadIdx.x & 31;
    const long ge = (long)blockIdx.x * 8 + wid;
    if (ge >= (long)EE) return;

    float gmax = sqrtf(__uint_as_float(g_maxbits));
    float inv_g = 1.f / (gmax + 0.001f);

    float* WS  = &wscr[wid][0];
    float* At  = WS;
    float* Bs  = WS + 64;
    float* Mm  = WS + 128;
    float* Tt  = WS + 192;
    float* cwt = WS + 256;
    float* cws = WS + 264;
    float* ctb = WS + 272;
    float* csb = WS + 296;

    int src = el[ge * 3 + 0];
    int tgt = el[ge * 3 + 1];
    int rel = el[ge * 3 + 2];

    // stage per-edge operands (independent gathers, full MLP)
    At[lane]      = ca[(long)tgt * 64 + lane];
    At[lane + 32] = ca[(long)tgt * 64 + lane + 32];
    Bs[lane]      = ca[(long)src * 64 + lane];
    Bs[lane + 32] = ca[(long)src * 64 + lane + 32];
    if (lane < 8) { cwt[lane] = cw[(long)tgt * 8 + lane]; cws[lane] = cw[(long)src * 8 + lane]; }
    if (lane < 24) { ctb[lane] = coords[(long)tgt * 24 + lane]; csb[lane] = coords[(long)src * 24 + lane]; }
    __syncwarp();

    // M[c][d] = (||ct_c - cs_d|| / (gmax+eps)) * cwt[c]*cws[d]
#pragma unroll
    for (int half = 0; half < 2; half++) {
        int idx = lane + half * 32;
        int c = idx >> 3, d = idx & 7;
        float dx = ctb[c * 3 + 0] - csb[d * 3 + 0];
        float dy = ctb[c * 3 + 1] - csb[d * 3 + 1];
        float dz = ctb[c * 3 + 2] - csb[d * 3 + 2];
        float ns = dx * dx + dy * dy + dz * dz;
        float nrm = (ns > 0.f) ? ns * rsqrtf(ns) : 0.f;
        Mm[idx] = nrm * inv_g * cwt[c] * cws[d];
    }
    __syncwarp();

    // T[a][d] = sum_c At[c][a] * M[c][d]
#pragma unroll
    for (int half = 0; half < 2; half++) {
        int idx = lane + half * 32;
        int a = idx >> 3, d = idx & 7;
        float t = 0.f;
#pragma unroll
        for (int c = 0; c < 8; c++) t = fmaf(At[c * 8 + a], Mm[c * 8 + d], t);
        Tt[idx] = t;
    }
    __syncwarp();

    // R[a][b] = sum_d T[a][d] * Bs[d][b]
    float r0 = 0.f, r1 = 0.f;
    {
        int a = lane >> 3, b = lane & 7;
#pragma unroll
        for (int d = 0; d < 8; d++) r0 = fmaf(Tt[a * 8 + d], Bs[d * 8 + b], r0);
        int idx = lane + 32;
        a = idx >> 3; b = idx & 7;
#pragma unroll
        for (int d = 0; d < 8; d++) r1 = fmaf(Tt[a * 8 + d], Bs[d * 8 + b], r1);
    }
    float ss = r0 * r0 + r1 * r1;
#pragma unroll
    for (int o = 16; o > 0; o >>= 1) ss += __shfl_xor_sync(0xffffffffu, ss, o);
    float invn = 1.f / (sqrtf(ss) + 0.001f);
    Mm[lane] = r0;           // reuse M as flattened R
    Mm[lane + 32] = r1;
    __syncwarp();

    // radial_out[j] = (R . rl_w[:,j]) * invn + rl_b[j]
    if (lane < 8) {
        float acc = 0.f;
#pragma unroll
        for (int k = 0; k < 64; k++) acc = fmaf(Mm[k], rl_w[k * 8 + lane], acc);
        g_rad[ge * 8 + lane] = acc * invn + rl_b[lane];
    }
    // coord_diff = coords[tgt] - pooled_col[src]
    if (lane < 24) {
        int k = lane % 3;
        g_cdiff[ge * 24 + lane] = ctb[lane] - g_pcol[(long)src * 3 + k];
    }
    if (lane == 0) {
        int cs = g_csum[tgt];
        int ts = cs - 1;
        ts = ts < 0 ? 0 : (ts > 7 ? 7 : ts);
        g_meta[ge] = make_int4(tgt, src, ts, __float_as_int(edge_weights[ge]));
        g_wr[ge] = w_r[rel];
    }
}

// ---------------- fused edge GEMM kernel ----------------
struct EdgeSmem {
    float ms1[TILE_E * MS];    // m1 / cf reuse
    float ms2[TILE_E * MS];    // m (post-GEMM2)
    float w1c[8 * 128];        // m_w1 rows 256..263 (radial part)
    float b1s[128];
    float rad[TILE_E * 8];
    float ef[TILE_E * 8];
    int   s_tgt[TILE_E];
    int   s_src[TILE_E];
    float s_ew[TILE_E];
    float s_wr[TILE_E];
    int   s_ts[TILE_E];
};

// 32 (edges) x 128 (cols) GEMM with packed-K FFMA2.
// 256 threads: eg = tid>>6 (4 groups of 8 edges), cg = tid&63 (64 col-pairs).
template <int KP>
__device__ __forceinline__ void tile_gemm(const float* __restrict__ src, int sstride,
                                          const unsigned long long* __restrict__ Wp,
                                          const float* __restrict__ bias,
                                          float* __restrict__ dst, int tid) {
    const int cg = tid & 63;
    const int eg = tid >> 6;
    unsigned long long acc0[8], acc1[8];
#pragma unroll
    for (int r = 0; r < 8; r++) { acc0[r] = 0ull; acc1[r] = 0ull; }

    const ulonglong2* Wv = (const ulonglong2*)Wp;  // [KP][64] of ulonglong2
    const float* srow = &src[eg * 8 * sstride];
#pragma unroll 4
    for (int kp = 0; kp < KP; kp++) {
        ulonglong2 w = Wv[kp * 64 + cg];           // cols 2cg, 2cg+1
#pragma unroll
        for (int r = 0; r < 8; r++) {
            unsigned long long xv = *(const unsigned long long*)&srow[r * sstride + kp * 2];
            FMA2(acc0[r], xv, w.x, acc0[r]);
            FMA2(acc1[r], xv, w.y, acc1[r]);
        }
    }
    float2 bb = *(const float2*)&bias[cg * 2];
#pragma unroll
    for (int r = 0; r < 8; r++) {
        float2 o;
        o.x = silu_f(lo_f(acc0[r]) + hi_f(acc0[r]) + bb.x);
        o.y = silu_f(lo_f(acc1[r]) + hi_f(acc1[r]) + bb.y);
        *(float2*)&dst[(eg * 8 + r) * MS + cg * 2] = o;
    }
}

__global__ __launch_bounds__(NTHR, 3)
void edge_kernel(const float* __restrict__ m_w1,
                 const float* __restrict__ m_b1,
                 const float* __restrict__ m_b2,
                 const float* __restrict__ c_b1) {
    extern __shared__ char smem_raw[];
    EdgeSmem& sm = *reinterpret_cast<EdgeSmem*>(smem_raw);

    const int tid = threadIdx.x;
    const long tileBase = (long)blockIdx.x * TILE_E;

    // stage W1c (radial rows) + b1
    for (int i = tid; i < 8 * 128; i += NTHR) sm.w1c[i] = m_w1[256 * 128 + i];
    if (tid < 128) sm.b1s[tid] = m_b1[tid];

    // load meta + rad (coalesced)
    if (tid < TILE_E) {
        long ge = tileBase + tid;
        if (ge < (long)EE) {
            int4 m = g_meta[ge];
            sm.s_tgt[tid] = m.x;
            sm.s_src[tid] = m.y;
            sm.s_ts[tid]  = m.z;
            sm.s_ew[tid]  = __int_as_float(m.w);
            sm.s_wr[tid]  = g_wr[ge];
        } else {
            sm.s_tgt[tid] = -1;
            sm.s_src[tid] = 0;
        }
    }
    {
        long base8 = tileBase * 8;
        if (tid < TILE_E * 8)
            sm.rad[tid] = (base8 + tid < (long)EE * 8) ? g_rad[base8 + tid] : 0.f;
    }
    __syncthreads();

    // ---- m1 = silu(Ah[tgt] + Bh[src] + rad @ W1c + b1) ----
    {
        const int e = tid >> 3;          // 32 edges
        const int q = tid & 7;           // 8 col-quarters of 16
        const int j0 = q * 16;
        int t = sm.s_tgt[e];
        int s = sm.s_src[e];
        float r[8];
#pragma unroll
        for (int k = 0; k < 8; k++) r[k] = sm.rad[e * 8 + k];
        if (t >= 0) {
#pragma unroll
            for (int v = 0; v < 4; v++) {
                int j = j0 + v * 4;
                float4 a  = *(const float4*)&g_Ah[(long)t * 128 + j];
                float4 b  = *(const float4*)&g_Bh[(long)s * 128 + j];
                float4 bb = *(const float4*)&sm.b1s[j];
                float4 acc;
                acc.x = a.x + b.x + bb.x;
                acc.y = a.y + b.y + bb.y;
                acc.z = a.z + b.z + bb.z;
                acc.w = a.w + b.w + bb.w;
#pragma unroll
                for (int k = 0; k < 8; k++) {
                    float4 w = *(const float4*)&sm.w1c[k * 128 + j];
                    acc.x = fmaf(r[k], w.x, acc.x);
                    acc.y = fmaf(r[k], w.y, acc.y);
                    acc.z = fmaf(r[k], w.z, acc.z);
                    acc.w = fmaf(r[k], w.w, acc.w);
                }
                float4 o;
                o.x = silu_f(acc.x); o.y = silu_f(acc.y);
                o.z = silu_f(acc.z); o.w = silu_f(acc.w);
                *(float4*)&sm.ms1[e * MS + j] = o;
            }
        } else {
#pragma unroll
            for (int v = 0; v < 4; v++)
                *(float4*)&sm.ms1[e * MS + j0 + v * 4] = make_float4(0.f, 0.f, 0.f, 0.f);
        }
    }
    __syncthreads();

    // ---- GEMM chain (packed-K FFMA2, 8 rows x 2 cols per thread) ----
    tile_gemm<64>(sm.ms1, MS, g_W2p,  m_b2, sm.ms2, tid);   // m  = silu(m1@W2+b2)
    __syncthreads();
    tile_gemm<64>(sm.ms2, MS, g_CW1p, c_b1, sm.ms1, tid);   // cf = silu(m@Cw1+Cb1)
    __syncthreads();

    // edge_feat = cf @ c_w2  (32 edges x 8), packed-K: one output per thread
    {
        int e = tid >> 3;
        int j = tid & 7;
        unsigned long long acc = 0ull;
#pragma unroll 8
        for (int kp = 0; kp < 64; kp++) {
            unsigned long long cf = *(const unsigned long long*)&sm.ms1[e * MS + kp * 2];
            FMA2(acc, cf, g_CW2p[kp * 8 + j], acc);
        }
        sm.ef[e * 8 + j] = lo_f(acc) + hi_f(acc);
    }
    __syncthreads();

    // ---- aggregation atomics ----
    // node_agg[tgt] += m * ew
    for (int idx = tid; idx < TILE_E * 128; idx += NTHR) {
        int e = idx >> 7, j = idx & 127;
        int t = sm.s_tgt[e];
        if (t >= 0)
            atomicAdd(&g_node_agg[(long)t * 128 + j], sm.ms2[e * MS + j] * sm.s_ew[e]);
    }
    // coord_sum[tgt] += w_r * coord_diff * pooled_edge
    if (tid < TILE_E * 8) {
        int e = tid >> 3, a = tid & 7;
        int t = sm.s_tgt[e];
        if (t >= 0) {
            int ts = sm.s_ts[e];
            int w = 8 - ts;
            int hi = a + w; if (hi > 8) hi = 8;
            float s = 0.f;
            for (int b = a; b < hi; b++) s += sm.ef[e * 8 + b];
            float pe = (s / (float)w) * sm.s_wr[e];
            long ge = tileBase + e;
#pragma unroll
            for (int k = 0; k < 3; k++)
                atomicAdd(&g_coord_sum[(long)t * 24 + a * 3 + k],
                          g_cdiff[ge * 24 + a * 3 + k] * pe);
        }
    }
    // cnt[tgt] += 1
    if (tid < TILE_E) {
        int t = sm.s_tgt[tid];
        if (t >= 0) atomicAdd(&g_cnt[t], 1.f);
    }
}

// ---------------- node epilogue: out GEMM + BN + silu + residuals ----------------
__global__ __launch_bounds__(NTHR, 3)
void node_out_kernel(const float* __restrict__ h,
                     const float* __restrict__ coords,
                     const float* __restrict__ het_b,
                     const float* __restrict__ gamma,
                     const float* __restrict__ beta,
                     float* __restrict__ out) {
    __shared__ float ag[32 * MS];
    const int tid = threadIdx.x;
    const int base = blockIdx.x * 32;
    const float INVS = 0.9999950000374996f;  // 1/sqrt(1+1e-5)

    for (int idx = tid; idx < 32 * 128; idx += NTHR) {
        int n = idx >> 7, k = idx & 127;
        int gn = base + n;
        ag[n * MS + k] = (gn < NN) ? g_node_agg[(long)gn * 128 + k] : 0.f;
    }
    __syncthreads();

    const int cg = tid & 63;
    const int ng = tid >> 6;
    unsigned long long acc0[8], acc1[8];
#pragma unroll
    for (int r = 0; r < 8; r++) { acc0[r] = 0ull; acc1[r] = 0ull; }
    const ulonglong2* Wv = (const ulonglong2*)g_HWp;
#pragma unroll 4
    for (int kp = 0; kp < 64; kp++) {
        ulonglong2 w = Wv[kp * 64 + cg];
#pragma unroll
        for (int r = 0; r < 8; r++) {
            unsigned long long xv = *(const unsigned long long*)&ag[(ng * 8 + r) * MS + kp * 2];
            FMA2(acc0[r], xv, w.x, acc0[r]);
            FMA2(acc1[r], xv, w.y, acc1[r]);
        }
    }
    int j0 = cg * 2;
    float2 hb = *(const float2*)&het_b[j0];
    float2 gm = *(const float2*)&gamma[j0];
    float2 bt = *(const float2*)&beta[j0];
#pragma unroll
    for (int r = 0; r < 8; r++) {
        int gn = base + ng * 8 + r;
        if (gn < NN) {
            float2 o;
            o.x = silu_f((lo_f(acc0[r]) + hi_f(acc0[r]) + hb.x) * INVS * gm.x + bt.x);
            o.y = silu_f((lo_f(acc1[r]) + hi_f(acc1[r]) + hb.y) * INVS * gm.y + bt.y);
            float2 hv = *(const float2*)&h[(long)gn * 128 + j0];
            o.x += hv.x; o.y += hv.y;
            *(float2*)&out[(long)gn * 128 + j0] = o;
        }
    }

    // coord_output = coords + coord_sum / max(cnt,1)
    for (int idx = tid; idx < 32 * 24; idx += NTHR) {
        int n = idx / 24, k = idx % 24;
        int gn = base + n;
        if (gn < NN) {
            float c = fmaxf(g_cnt[gn], 1.f);
            out[(long)NN * 128 + (long)gn * 24 + k] =
                coords[(long)gn * 24 + k] + g_coord_sum[(long)gn * 24 + k] / c;
        }
    }
}

// ---------------- launch ----------------
extern "C" void kernel_launch(void* const* d_in, const int* in_sizes, int n_in,
                              void* d_out, int out_size) {
    (void)in_sizes; (void)n_in; (void)out_size;
    const float* h      = (const float*)d_in[0];
    const float* coords = (const float*)d_in[1];
    const float* ca     = (const float*)d_in[2];
    const float* cw     = (const float*)d_in[3];
    const float* ew     = (const float*)d_in[4];
    const int*   el     = (const int*)d_in[5];
    const float* rl_w   = (const float*)d_in[6];
    const float* rl_b   = (const float*)d_in[7];
    const float* m_w1   = (const float*)d_in[8];
    const float* m_b1   = (const float*)d_in[9];
    const float* m_w2   = (const float*)d_in[10];
    const float* m_b2   = (const float*)d_in[11];
    const float* c_w1   = (const float*)d_in[12];
    const float* c_b1   = (const float*)d_in[13];
    const float* c_w2   = (const float*)d_in[14];
    const float* het_w  = (const float*)d_in[15];
    const float* het_b  = (const float*)d_in[16];
    const float* gamma  = (const float*)d_in[17];
    const float* beta   = (const float*)d_in[18];
    const float* w_r    = (const float*)d_in[19];
    float* out = (float*)d_out;

    cudaFuncSetAttribute(edge_kernel, cudaFuncAttributeMaxDynamicSharedMemorySize,
                         (int)sizeof(EdgeSmem));

    zero_kernel<<<2048, 256>>>();
    pack_kernel<<<132, 256>>>(m_w1, m_w2, c_w1, c_w2, het_w);
    node_pre_kernel<<<(NN + 255) / 256, 256>>>(coords, cw);
    node_gemm_kernel<<<(NN + 31) / 32, NTHR>>>(h);
    max_kernel<<<(EE + 255) / 256, 256>>>(coords, el);
    edge_pre_kernel<<<(EE + 7) / 8, 256>>>(coords, ca, cw, ew, el, rl_w, rl_b, w_r);
    edge_kernel<<<(EE + TILE_E - 1) / TILE_E, NTHR, sizeof(EdgeSmem)>>>(
        m_w1, m_b1, m_b2, c_b1);
    node_out_kernel<<<(NN + 31) / 32, NTHR>>>(h, coords, het_b, gamma, beta, out);
}